// round 1
// baseline (speedup 1.0000x reference)
#include <cuda_runtime.h>
#include <math.h>
#include <stdint.h>

#define N0 4096
#define CH 256

// ---------------- scratch (static device globals; no allocations) ----------------
__device__ float g_A0[N0 * N0];
__device__ float g_A1[2048 * 2048];
__device__ float g_A2[1024 * 1024];
__device__ float g_A3[512 * 512];
__device__ float g_Bp[2048 * 4096];
__device__ float g_Bc[4096 * 2048];
__device__ float g_X0[N0 * CH];
__device__ float g_X1[2048 * CH];
__device__ float g_X2[1024 * CH];
__device__ float g_Xc[N0 * CH];
__device__ float g_XW[N0 * CH];
__device__ float g_Xin[N0 * CH];
__device__ float g_deg[4][N0];
__device__ float g_dinv[4][N0];
__device__ float g_fil[4][N0];
__device__ float g_s[N0];
__device__ float g_pn[1];
__device__ int   g_perm[3][2048];

static inline int cdiv(int a, int b) { return (a + b - 1) / b; }

// ---------------- small utility kernels ----------------
__global__ void zero_kernel(float* __restrict__ p, int n) {
    int i = blockIdx.x * blockDim.x + threadIdx.x;
    if (i < n) p[i] = 0.f;
}

__global__ void copy_kernel(float* __restrict__ dst, const float* __restrict__ src, int n) {
    int i = blockIdx.x * blockDim.x + threadIdx.x;
    if (i < n) dst[i] = src[i];
}

__global__ void edge_kernel(const int* __restrict__ ei, int E, float* __restrict__ A) {
    int i = blockIdx.x * blockDim.x + threadIdx.x;
    if (i < E) atomicAdd(&A[(size_t)ei[i] * N0 + ei[E + i]], 1.0f);
}

// deg[c] += sum over a 256-row stripe of A[:, c]; entries are integers -> exact, order-free
__global__ void colsum_kernel(const float* __restrict__ A, int n, float* __restrict__ deg) {
    int c = blockIdx.x * 256 + threadIdx.x;
    int r0 = blockIdx.y * 256;
    float sum = 0.f;
    for (int r = r0; r < r0 + 256; r++) sum += A[(size_t)r * n + c];
    atomicAdd(&deg[c], sum);
}

__global__ void finalize_deg_kernel(const float* __restrict__ A, int n,
                                    const float* __restrict__ deg,
                                    float* __restrict__ dinv, float* __restrict__ fil) {
    int c = blockIdx.x * blockDim.x + threadIdx.x;
    if (c >= n) return;
    float f = (A[(size_t)c * n + c] == 0.f) ? 2.f : 0.f;
    float d = deg[c] + f;
    dinv[c] = rsqrtf(d);
    fil[c] = f;
}

__global__ void pnorm_kernel(const float* __restrict__ p, float* __restrict__ pn) {
    __shared__ float red[8];
    int tid = threadIdx.x;
    float v = p[tid];
    v *= v;
#pragma unroll
    for (int o = 16; o; o >>= 1) v += __shfl_down_sync(0xffffffffu, v, o);
    if ((tid & 31) == 0) red[tid >> 5] = v;
    __syncthreads();
    if (tid < 8) {
        float a = red[tid];
#pragma unroll
        for (int o = 4; o; o >>= 1) a += __shfl_down_sync(0xffu, a, o);
        if (tid == 0) pn[0] = rsqrtf(a);  // inverse norm
    }
}

// one warp per row: s[i] = x[i,:] . p
__global__ void score_kernel(const float* __restrict__ x, const float* __restrict__ p,
                             int n, float* __restrict__ s) {
    int warp = (blockIdx.x * blockDim.x + threadIdx.x) >> 5;
    int lane = threadIdx.x & 31;
    if (warp >= n) return;
    const float* row = x + (size_t)warp * CH;
    float acc = 0.f;
#pragma unroll
    for (int q = 0; q < 8; q++) acc += row[lane + 32 * q] * p[lane + 32 * q];
#pragma unroll
    for (int o = 16; o; o >>= 1) acc += __shfl_down_sync(0xffffffffu, acc, o);
    if (lane == 0) s[warp] = acc;
}

// one-block bitonic sort of 4096 (score,index) keys, descending score, ascending index on ties
__global__ void sort_topk_kernel(const float* __restrict__ s, int n, int k, int* __restrict__ perm) {
    __shared__ unsigned long long key[4096];
    int tid = threadIdx.x;
    for (int t = tid; t < 4096; t += blockDim.x) {
        unsigned long long kk;
        if (t < n) {
            unsigned int b = __float_as_uint(s[t]);
            unsigned int u = (b & 0x80000000u) ? ~b : (b | 0x80000000u);
            kk = ((unsigned long long)u << 32) | (unsigned int)(~(unsigned int)t);
        } else {
            kk = 0ull;  // smaller than any real key -> sorts to the end
        }
        key[t] = kk;
    }
    __syncthreads();
    for (int k2 = 2; k2 <= 4096; k2 <<= 1) {
        for (int j = k2 >> 1; j >= 1; j >>= 1) {
            for (int t = tid; t < 4096; t += blockDim.x) {
                int ixj = t ^ j;
                if (ixj > t) {
                    bool desc = ((t & k2) == 0);
                    unsigned long long a = key[t], b = key[ixj];
                    bool sw = desc ? (a < b) : (a > b);
                    if (sw) { key[t] = b; key[ixj] = a; }
                }
            }
            __syncthreads();
        }
    }
    for (int t = tid; t < k; t += blockDim.x)
        perm[t] = (int)(~(unsigned int)(key[t] & 0xFFFFFFFFu));
}

__global__ void gather_x_kernel(const float* __restrict__ xold, float* __restrict__ xnew,
                                const int* __restrict__ perm, const float* __restrict__ s,
                                const float* __restrict__ pninv, int k) {
    int idx = blockIdx.x * blockDim.x + threadIdx.x;
    if (idx >= k * CH) return;
    int i = idx >> 8;
    int j = idx & 255;
    int pi = perm[i];
    float g = tanhf(s[pi] * pninv[0]);
    xnew[idx] = xold[(size_t)pi * CH + j] * g;
}

__global__ void gather_bp_kernel(const float* __restrict__ A, int n,
                                 const int* __restrict__ perm, int k, float* __restrict__ Bp) {
    int idx = blockIdx.x * blockDim.x + threadIdx.x;
    if (idx >= k * n) return;
    int i = idx / n;
    int c = idx - i * n;
    Bp[idx] = A[(size_t)perm[i] * n + c];
}

__global__ void gather_bc_kernel(const float* __restrict__ A, int n,
                                 const int* __restrict__ perm, int k, float* __restrict__ Bc) {
    int idx = blockIdx.x * blockDim.x + threadIdx.x;
    if (idx >= n * k) return;
    int r = idx / k;
    int j = idx - r * k;
    Bc[idx] = A[(size_t)r * n + perm[j]];
}

__global__ void scatter_add_kernel(float* __restrict__ Xin, const float* __restrict__ xcur,
                                   const int* __restrict__ perm, int k) {
    int idx = blockIdx.x * blockDim.x + threadIdx.x;
    if (idx >= k * CH) return;
    int i = idx >> 8;
    int j = idx & 255;
    Xin[(size_t)perm[i] * CH + j] += xcur[idx];
}

// deterministic mean over rows (single block)
__global__ void mean_kernel(const float* __restrict__ x, int n, float* __restrict__ out) {
    int j = threadIdx.x;
    float s0 = 0.f, s1 = 0.f, s2 = 0.f, s3 = 0.f;
    for (int r = 0; r < n; r += 4) {
        s0 += x[(size_t)(r + 0) * CH + j];
        s1 += x[(size_t)(r + 1) * CH + j];
        s2 += x[(size_t)(r + 2) * CH + j];
        s3 += x[(size_t)(r + 3) * CH + j];
    }
    out[j] = (s0 + s1 + s2 + s3) / (float)n;
}

// ---------------- tiled fp32 GEMM, 128x128x8, 8x8 microtile ----------------
// TRANSA=0: A element (m,k) at A[m*lda + k]   (row-major)
// TRANSA=1: A element (m,k) at A[k*lda + m]   (reads adjacency transposed)
// MODE=1: C = dinv[m] * acc                                  (z = D^-1/2 * XW)
// MODE=2: C = dinv[m]*(acc + fil[m]*B[m,c]) + bias[c], relu  (GCN output)
// MODE=3: C = (m==c) ? 0 : acc + 2*B[perm[m], c]             (pooled augment)
template <int TRANSA, int MODE>
__global__ void __launch_bounds__(256, 2)
gemm_k(const float* __restrict__ A, int lda,
       const float* __restrict__ B, int ldb,
       float* __restrict__ C, int ldc, int K,
       const float* __restrict__ dinv, const float* __restrict__ fil,
       const float* __restrict__ bias, const int* __restrict__ perm,
       int relu) {
    constexpr int BM = 128, BN = 128, BK = 8;
    __shared__ float As[BK][BM + 4];
    __shared__ float Bs[BK][BN + 4];
    const int m0 = blockIdx.y * BM;
    const int j0 = blockIdx.x * BN;
    const int tid = threadIdx.x;
    const int ty = tid >> 4;
    const int tx = tid & 15;

    float acc[8][8];
#pragma unroll
    for (int i = 0; i < 8; i++)
#pragma unroll
        for (int j = 0; j < 8; j++) acc[i][j] = 0.f;

    for (int k0 = 0; k0 < K; k0 += BK) {
        if (TRANSA) {
            const int kk = tid >> 5;
            const int mm = (tid & 31) << 2;
            float4 v = *(const float4*)(A + (size_t)(k0 + kk) * lda + (m0 + mm));
            *(float4*)&As[kk][mm] = v;
        } else {
            const int mm = tid >> 1;
            const int kq = (tid & 1) << 2;
            float4 v = *(const float4*)(A + (size_t)(m0 + mm) * lda + (k0 + kq));
            As[kq + 0][mm] = v.x;
            As[kq + 1][mm] = v.y;
            As[kq + 2][mm] = v.z;
            As[kq + 3][mm] = v.w;
        }
        {
            const int kk = tid >> 5;
            const int jj = (tid & 31) << 2;
            float4 v = *(const float4*)(B + (size_t)(k0 + kk) * ldb + (j0 + jj));
            *(float4*)&Bs[kk][jj] = v;
        }
        __syncthreads();
#pragma unroll
        for (int kk = 0; kk < BK; kk++) {
            float ra[8], rb[8];
#pragma unroll
            for (int i = 0; i < 8; i++) ra[i] = As[kk][ty * 8 + i];
#pragma unroll
            for (int j = 0; j < 8; j++) rb[j] = Bs[kk][tx * 8 + j];
#pragma unroll
            for (int i = 0; i < 8; i++)
#pragma unroll
                for (int j = 0; j < 8; j++) acc[i][j] = fmaf(ra[i], rb[j], acc[i][j]);
        }
        __syncthreads();
    }

#pragma unroll
    for (int i = 0; i < 8; i++) {
        const int m = m0 + ty * 8 + i;
#pragma unroll
        for (int j = 0; j < 8; j++) {
            const int c = j0 + tx * 8 + j;
            float v = acc[i][j];
            if (MODE == 1) v *= dinv[m];
            if (MODE == 2) {
                v = dinv[m] * (v + fil[m] * B[(size_t)m * ldb + c]) + bias[c];
                if (relu) v = fmaxf(v, 0.f);
            }
            if (MODE == 3) {
                v = (m == c) ? 0.f : (v + 2.f * B[(size_t)perm[m] * ldb + c]);
            }
            C[(size_t)m * ldc + c] = v;
        }
    }
}

// ---------------- host orchestration ----------------
#define SYM(p, s)                                  \
    do {                                           \
        void* _t = nullptr;                        \
        cudaGetSymbolAddress(&_t, s);              \
        p = (decltype(p))_t;                       \
    } while (0)

extern "C" void kernel_launch(void* const* d_in, const int* in_sizes, int n_in,
                              void* d_out, int out_size) {
    const float* x_in = (const float*)d_in[0];
    const int* ei     = (const int*)d_in[1];
    const float* w_d0 = (const float*)d_in[3];
    const float* b_d0 = (const float*)d_in[4];
    const float* w_d  = (const float*)d_in[5];
    const float* b_d  = (const float*)d_in[6];
    const float* p_at = (const float*)d_in[7];
    const float* w_u  = (const float*)d_in[8];
    const float* b_u  = (const float*)d_in[9];
    float* out = (float*)d_out;
    const int E = in_sizes[1] / 2;

    float *A0, *A1, *A2, *A3, *Bp, *Bc, *X0, *X1, *X2, *Xc, *XW, *Xin;
    float *deg, *dinv, *fil, *sc, *pn;
    int* perm;
    SYM(A0, g_A0);  SYM(A1, g_A1);  SYM(A2, g_A2);  SYM(A3, g_A3);
    SYM(Bp, g_Bp);  SYM(Bc, g_Bc);
    SYM(X0, g_X0);  SYM(X1, g_X1);  SYM(X2, g_X2);
    SYM(Xc, g_Xc);  SYM(XW, g_XW);  SYM(Xin, g_Xin);
    SYM(deg, g_deg); SYM(dinv, g_dinv); SYM(fil, g_fil);
    SYM(sc, g_s);   SYM(pn, g_pn);  SYM(perm, g_perm);

    float* Alv[4] = {A0, A1, A2, A3};
    float* Xs[3] = {X0, X1, X2};
    const int ns[4] = {4096, 2048, 1024, 512};

    // build dense A0 from edge list
    zero_kernel<<<cdiv(N0 * N0, 256), 256>>>(A0, N0 * N0);
    edge_kernel<<<cdiv(E, 256), 256>>>(ei, E, A0);

    auto prep = [&](int lvl) {
        int n = ns[lvl];
        zero_kernel<<<cdiv(n, 256), 256>>>(deg + lvl * N0, n);
        colsum_kernel<<<dim3(n / 256, n / 256), 256>>>(Alv[lvl], n, deg + lvl * N0);
        finalize_deg_kernel<<<cdiv(n, 256), 256>>>(Alv[lvl], n, deg + lvl * N0,
                                                   dinv + lvl * N0, fil + lvl * N0);
    };
    auto gcn = [&](int lvl, const float* Xsrc, int Kin, const float* W,
                   const float* bias, float* Y, int relu) {
        int n = ns[lvl];
        // z = D^-1/2 * (X @ W)
        gemm_k<0, 1><<<dim3(CH / 128, n / 128), 256>>>(Xsrc, Kin, W, CH, XW, CH, Kin,
                                                       dinv + lvl * N0, nullptr, nullptr,
                                                       nullptr, 0);
        // Y = D^-1/2 * (A^T z + fill .* z) + b  (relu optional)
        gemm_k<1, 2><<<dim3(CH / 128, n / 128), 256>>>(Alv[lvl], n, XW, CH, Y, CH, n,
                                                       dinv + lvl * N0, fil + lvl * N0,
                                                       bias, nullptr, relu);
    };

    prep(0);
    gcn(0, x_in, 128, w_d0, b_d0, X0, 1);

    // ---- down path ----
    for (int i = 0; i < 3; i++) {
        int n = ns[i], k = ns[i + 1];
        int* pm = perm + i * 2048;
        const float* pvec = p_at + i * CH;

        pnorm_kernel<<<1, 256>>>(pvec, pn);
        score_kernel<<<n / 8, 256>>>(Xs[i], pvec, n, sc);
        sort_topk_kernel<<<1, 1024>>>(sc, n, k, pm);
        gather_x_kernel<<<cdiv(k * CH, 256), 256>>>(Xs[i], Xc, pm, sc, pn, k);

        // pooled augment: A_new = Bp @ Bc (+ 2*A[pi,pj], zero diag)
        gather_bp_kernel<<<cdiv(k * n, 256), 256>>>(Alv[i], n, pm, k, Bp);
        gather_bc_kernel<<<cdiv(n * k, 256), 256>>>(Alv[i], n, pm, k, Bc);
        gemm_k<0, 3><<<dim3(k / 128, k / 128), 256>>>(Bp, n, Bc, k, Alv[i + 1], k, n,
                                                      nullptr, nullptr, nullptr, pm, 0);
        prep(i + 1);
        if (i < 2)
            gcn(i + 1, Xc, CH, w_d + i * CH * CH, b_d + i * CH, Xs[i + 1], 1);
        else
            gcn(3, Xc, CH, w_d + 2 * CH * CH, b_d + 2 * CH, Xc, 1);  // current x -> Xc (512)
    }

    // ---- up path ----
    for (int i = 0; i < 3; i++) {
        int j = 2 - i;
        int nj = ns[j];       // res rows
        int kj = ns[j + 1];   // current x rows
        copy_kernel<<<cdiv(nj * CH, 256), 256>>>(Xin, Xs[j], nj * CH);
        scatter_add_kernel<<<cdiv(kj * CH, 256), 256>>>(Xin, Xc, perm + j * 2048, kj);
        gcn(j, Xin, CH, w_u + i * CH * CH, b_u + i * CH, Xc, (i < 2) ? 1 : 0);
    }

    mean_kernel<<<1, 256>>>(Xc, N0, out);
}

// round 2
// speedup vs baseline: 2.4679x; 2.4679x over previous
#include <cuda_runtime.h>
#include <cuda_bf16.h>
#include <math.h>
#include <stdint.h>
#include <type_traits>

#define N0 4096
#define CH 256

using bf16 = __nv_bfloat16;

// ---------------- scratch (static device globals; no allocations) ----------------
__device__ float g_A0f[(size_t)N0 * N0];
__device__ bf16  g_A0[(size_t)N0 * N0];
__device__ bf16  g_A1[2048 * 2048];
__device__ bf16  g_A2[1024 * 1024];
__device__ bf16  g_A3[512 * 512];
__device__ bf16  g_AT0[(size_t)N0 * N0];
__device__ bf16  g_AT1[2048 * 2048];
__device__ bf16  g_AT2[1024 * 1024];
__device__ bf16  g_AT3[512 * 512];
__device__ bf16  g_Bp[2048 * 4096];
__device__ bf16  g_BpAT[2048 * 4096];
__device__ float g_X0[N0 * CH];
__device__ float g_X1[2048 * CH];
__device__ float g_X2[1024 * CH];
__device__ float g_Xc[N0 * CH];
__device__ float g_XW[N0 * CH];
__device__ float g_Xin[N0 * CH];
__device__ float g_deg[4][N0];
__device__ float g_dinv[4][N0];
__device__ float g_fil[4][N0];
__device__ float g_s[N0];
__device__ float g_pn[1];
__device__ int   g_perm[3][2048];

static inline int cdiv(int a, int b) { return (a + b - 1) / b; }

// ---------------- small utility kernels ----------------
__global__ void zero_kernel(float* __restrict__ p, size_t n) {
    size_t i = (size_t)blockIdx.x * blockDim.x + threadIdx.x;
    if (i < n) p[i] = 0.f;
}

__global__ void copy_kernel(float* __restrict__ dst, const float* __restrict__ src, int n) {
    int i = blockIdx.x * blockDim.x + threadIdx.x;
    if (i < n) dst[i] = src[i];
}

__global__ void edge_kernel(const int* __restrict__ ei, int E, float* __restrict__ A) {
    int i = blockIdx.x * blockDim.x + threadIdx.x;
    if (i < E) atomicAdd(&A[(size_t)ei[i] * N0 + ei[E + i]], 1.0f);
}

__global__ void f2bf_kernel(const float* __restrict__ in, bf16* __restrict__ out, size_t n) {
    size_t i = (size_t)blockIdx.x * blockDim.x + threadIdx.x;
    if (i < n) out[i] = __float2bfloat16(in[i]);
}

// 32x32 tiled bf16 transpose
__global__ void transpose_bf16(const uint16_t* __restrict__ in, uint16_t* __restrict__ out, int n) {
    __shared__ uint16_t t[32][33];
    int bx = blockIdx.x * 32, by = blockIdx.y * 32;
    int x = bx + threadIdx.x;
    for (int ry = threadIdx.y; ry < 32; ry += 8)
        t[ry][threadIdx.x] = in[(size_t)(by + ry) * n + x];
    __syncthreads();
    int xo = by + threadIdx.x;
    for (int ry = threadIdx.y; ry < 32; ry += 8)
        out[(size_t)(bx + ry) * n + xo] = t[threadIdx.x][ry];
}

// deg[c] += 256-row stripe column sums of bf16 A (integer values -> exact, order-free)
__global__ void colsum_bf16(const bf16* __restrict__ A, int n, float* __restrict__ deg) {
    int c = blockIdx.x * 256 + threadIdx.x;
    int r0 = blockIdx.y * 256;
    float sum = 0.f;
    for (int r = r0; r < r0 + 256; r++) sum += __bfloat162float(A[(size_t)r * n + c]);
    atomicAdd(&deg[c], sum);
}

__global__ void finalize_deg_kernel(const bf16* __restrict__ A, int n,
                                    const float* __restrict__ deg,
                                    float* __restrict__ dinv, float* __restrict__ fil) {
    int c = blockIdx.x * blockDim.x + threadIdx.x;
    if (c >= n) return;
    float f = (__bfloat162float(A[(size_t)c * n + c]) == 0.f) ? 2.f : 0.f;
    float d = deg[c] + f;
    dinv[c] = rsqrtf(d);
    fil[c] = f;
}

__global__ void pnorm_kernel(const float* __restrict__ p, float* __restrict__ pn) {
    __shared__ float red[8];
    int tid = threadIdx.x;
    float v = p[tid];
    v *= v;
#pragma unroll
    for (int o = 16; o; o >>= 1) v += __shfl_down_sync(0xffffffffu, v, o);
    if ((tid & 31) == 0) red[tid >> 5] = v;
    __syncthreads();
    if (tid < 8) {
        float a = red[tid];
#pragma unroll
        for (int o = 4; o; o >>= 1) a += __shfl_down_sync(0xffu, a, o);
        if (tid == 0) pn[0] = rsqrtf(a);  // inverse norm
    }
}

__global__ void score_kernel(const float* __restrict__ x, const float* __restrict__ p,
                             int n, float* __restrict__ s) {
    int warp = (blockIdx.x * blockDim.x + threadIdx.x) >> 5;
    int lane = threadIdx.x & 31;
    if (warp >= n) return;
    const float* row = x + (size_t)warp * CH;
    float acc = 0.f;
#pragma unroll
    for (int q = 0; q < 8; q++) acc += row[lane + 32 * q] * p[lane + 32 * q];
#pragma unroll
    for (int o = 16; o; o >>= 1) acc += __shfl_down_sync(0xffffffffu, acc, o);
    if (lane == 0) s[warp] = acc;
}

// one-block bitonic sort of 4096 (score,index) keys, descending score, ascending index on ties
__global__ void sort_topk_kernel(const float* __restrict__ s, int n, int k, int* __restrict__ perm) {
    __shared__ unsigned long long key[4096];
    int tid = threadIdx.x;
    for (int t = tid; t < 4096; t += blockDim.x) {
        unsigned long long kk;
        if (t < n) {
            unsigned int b = __float_as_uint(s[t]);
            unsigned int u = (b & 0x80000000u) ? ~b : (b | 0x80000000u);
            kk = ((unsigned long long)u << 32) | (unsigned int)(~(unsigned int)t);
        } else {
            kk = 0ull;
        }
        key[t] = kk;
    }
    __syncthreads();
    for (int k2 = 2; k2 <= 4096; k2 <<= 1) {
        for (int j = k2 >> 1; j >= 1; j >>= 1) {
            for (int t = tid; t < 4096; t += blockDim.x) {
                int ixj = t ^ j;
                if (ixj > t) {
                    bool desc = ((t & k2) == 0);
                    unsigned long long a = key[t], b = key[ixj];
                    bool sw = desc ? (a < b) : (a > b);
                    if (sw) { key[t] = b; key[ixj] = a; }
                }
            }
            __syncthreads();
        }
    }
    for (int t = tid; t < k; t += blockDim.x)
        perm[t] = (int)(~(unsigned int)(key[t] & 0xFFFFFFFFu));
}

__global__ void gather_x_kernel(const float* __restrict__ xold, float* __restrict__ xnew,
                                const int* __restrict__ perm, const float* __restrict__ s,
                                const float* __restrict__ pninv, int k) {
    int idx = blockIdx.x * blockDim.x + threadIdx.x;
    if (idx >= k * CH) return;
    int i = idx >> 8;
    int j = idx & 255;
    int pi = perm[i];
    float g = tanhf(s[pi] * pninv[0]);
    xnew[idx] = xold[(size_t)pi * CH + j] * g;
}

// row gather of bf16 matrix: out[i,:] = A[perm[i],:]  (2 bf16 per thread)
__global__ void gather_rows_bf16(const bf16* __restrict__ A, int n,
                                 const int* __restrict__ perm, int k, bf16* __restrict__ out) {
    int n2 = n >> 1;
    int idx = blockIdx.x * blockDim.x + threadIdx.x;
    if (idx >= k * n2) return;
    int i = idx / n2;
    int c2 = idx - i * n2;
    ((uint32_t*)out)[(size_t)i * n2 + c2] =
        ((const uint32_t*)(A + (size_t)perm[i] * n))[c2];
}

__global__ void scatter_add_kernel(float* __restrict__ Xin, const float* __restrict__ xcur,
                                   const int* __restrict__ perm, int k) {
    int idx = blockIdx.x * blockDim.x + threadIdx.x;
    if (idx >= k * CH) return;
    int i = idx >> 8;
    int j = idx & 255;
    Xin[(size_t)perm[i] * CH + j] += xcur[idx];
}

__global__ void mean_kernel(const float* __restrict__ x, int n, float* __restrict__ out) {
    int j = threadIdx.x;
    float s0 = 0.f, s1 = 0.f, s2 = 0.f, s3 = 0.f;
    for (int r = 0; r < n; r += 4) {
        s0 += x[(size_t)(r + 0) * CH + j];
        s1 += x[(size_t)(r + 1) * CH + j];
        s2 += x[(size_t)(r + 2) * CH + j];
        s3 += x[(size_t)(r + 3) * CH + j];
    }
    out[j] = (s0 + s1 + s2 + s3) / (float)n;
}

// ---------------- bf16 tensor-core GEMM (mma.sync m16n8k16), 128x128x32 ----------------
// TA=float: A fp32 [M][K], split into (hi,lo) bf16 on load (SA=2)
// TA=bf16 : A bf16  [M][K], exact (SA=1)
// TB=float: B fp32 [K][N], split (SB=2)
// TB=bf16 : B bf16  [N][K] (transposed source), exact (SB=1)
// products: all (pa,pb) with pa+pb<2  -> 1, 2, or 3 passes (lo*lo dropped)
// MODE=1: C[m,c] = dinv[m]*acc                                (fp32)
// MODE=2: C[m,c] = dinv[m]*(acc + fil[m]*zaux[m,c]) + bias[c] (+relu) (fp32)
// MODE=3: C[m,c] = (m==c)?0 : acc + 2*adj[m*lda + perm[c]]    (bf16 out)
template <typename TA, typename TB, int MODE>
__global__ void __launch_bounds__(256, 2) mma_gemm(
    const void* __restrict__ Ap, int lda,
    const void* __restrict__ Bptr, int ldb,
    void* __restrict__ Cp, int ldc, int K,
    const float* __restrict__ dinv, const float* __restrict__ fil,
    const float* __restrict__ bias, const float* __restrict__ zaux,
    const bf16* __restrict__ adj, const int* __restrict__ perm, int relu) {
    constexpr int SA = std::is_same<TA, float>::value ? 2 : 1;
    constexpr int SB = std::is_same<TB, float>::value ? 2 : 1;
    constexpr int BM = 128, BN = 128, BK = 32, BKP = 40, BNP = 136;

    __shared__ uint16_t As[SA][BM][BKP];
    __shared__ uint32_t Bs[SB][BK / 2][BNP];

    const int tid = threadIdx.x;
    const int lane = tid & 31, warp = tid >> 5;
    const int g = lane >> 2, tg = lane & 3;
    const int wm = warp >> 2, wn = warp & 3;
    const int m0 = blockIdx.y * BM, j0 = blockIdx.x * BN;

    float acc[4][4][4];
#pragma unroll
    for (int a = 0; a < 4; a++)
#pragma unroll
        for (int b = 0; b < 4; b++)
#pragma unroll
            for (int e = 0; e < 4; e++) acc[a][b][e] = 0.f;

    for (int k0 = 0; k0 < K; k0 += BK) {
        // ---- stage A tile
        {
            int m = tid >> 1, koff = (tid & 1) * 16;
            if (SA == 2) {
                const float* src = (const float*)Ap + (size_t)(m0 + m) * lda + k0 + koff;
#pragma unroll
                for (int q = 0; q < 4; q++) {
                    float4 v = *(const float4*)(src + 4 * q);
                    float vv[4] = {v.x, v.y, v.z, v.w};
#pragma unroll
                    for (int e = 0; e < 4; e++) {
                        bf16 h = __float2bfloat16(vv[e]);
                        bf16 l = __float2bfloat16(vv[e] - __bfloat162float(h));
                        As[0][m][koff + 4 * q + e] = __bfloat16_as_ushort(h);
                        As[SA - 1][m][koff + 4 * q + e] = __bfloat16_as_ushort(l);
                    }
                }
            } else {
                const bf16* src = (const bf16*)Ap + (size_t)(m0 + m) * lda + k0 + koff;
                uint4 v0 = *(const uint4*)src;
                uint4 v1 = *(const uint4*)(src + 8);
                uint32_t* dstw = (uint32_t*)&As[0][m][koff];
                dstw[0] = v0.x; dstw[1] = v0.y; dstw[2] = v0.z; dstw[3] = v0.w;
                dstw[4] = v1.x; dstw[5] = v1.y; dstw[6] = v1.z; dstw[7] = v1.w;
            }
        }
        // ---- stage B tile
        if (SB == 2) {
            int kp = tid >> 4, noff = (tid & 15) * 8;
            const float* r0 = (const float*)Bptr + (size_t)(k0 + 2 * kp) * ldb + j0 + noff;
            const float* r1 = r0 + ldb;
            float4 a0 = *(const float4*)r0, a1 = *(const float4*)(r0 + 4);
            float4 b0 = *(const float4*)r1, b1 = *(const float4*)(r1 + 4);
            float u[8] = {a0.x, a0.y, a0.z, a0.w, a1.x, a1.y, a1.z, a1.w};
            float w[8] = {b0.x, b0.y, b0.z, b0.w, b1.x, b1.y, b1.z, b1.w};
#pragma unroll
            for (int e = 0; e < 8; e++) {
                bf16 uh = __float2bfloat16(u[e]);
                bf16 wh = __float2bfloat16(w[e]);
                bf16 ul = __float2bfloat16(u[e] - __bfloat162float(uh));
                bf16 wl = __float2bfloat16(w[e] - __bfloat162float(wh));
                Bs[0][kp][noff + e] =
                    ((uint32_t)__bfloat16_as_ushort(wh) << 16) | __bfloat16_as_ushort(uh);
                Bs[SB - 1][kp][noff + e] =
                    ((uint32_t)__bfloat16_as_ushort(wl) << 16) | __bfloat16_as_ushort(ul);
            }
        } else {
#pragma unroll
            for (int h = 0; h < 2; h++) {
                int n = (tid >> 2) + h * 64;
                int koff = (tid & 3) * 8;
                const bf16* src = (const bf16*)Bptr + (size_t)(j0 + n) * ldb + k0 + koff;
                uint4 v = *(const uint4*)src;  // 4 packed (k,k+1) bf16 pairs
                uint32_t ww[4] = {v.x, v.y, v.z, v.w};
#pragma unroll
                for (int i = 0; i < 4; i++) Bs[0][(koff >> 1) + i][n] = ww[i];
            }
        }
        __syncthreads();

        // ---- compute: two k16 sub-steps
#pragma unroll
        for (int kk2 = 0; kk2 < 16; kk2 += 8) {
#pragma unroll
            for (int pa = 0; pa < SA; pa++) {
                uint32_t afr[4][4];
#pragma unroll
                for (int mf = 0; mf < 4; mf++) {
                    int m = wm * 64 + mf * 16 + g;
                    int kc = kk2 * 2 + 2 * tg;
                    afr[mf][0] = *(const uint32_t*)&As[pa][m][kc];
                    afr[mf][1] = *(const uint32_t*)&As[pa][m + 8][kc];
                    afr[mf][2] = *(const uint32_t*)&As[pa][m][kc + 8];
                    afr[mf][3] = *(const uint32_t*)&As[pa][m + 8][kc + 8];
                }
#pragma unroll
                for (int pb = 0; pb < SB; pb++) {
                    if (pa + pb >= 2) continue;
                    uint32_t bfr[4][2];
#pragma unroll
                    for (int nf = 0; nf < 4; nf++) {
                        int n = wn * 32 + nf * 8 + g;
                        bfr[nf][0] = Bs[pb][kk2 + tg][n];
                        bfr[nf][1] = Bs[pb][kk2 + tg + 4][n];
                    }
#pragma unroll
                    for (int mf = 0; mf < 4; mf++)
#pragma unroll
                        for (int nf = 0; nf < 4; nf++)
                            asm volatile(
                                "mma.sync.aligned.m16n8k16.row.col.f32.bf16.bf16.f32 "
                                "{%0,%1,%2,%3},{%4,%5,%6,%7},{%8,%9},{%0,%1,%2,%3};"
                                : "+f"(acc[mf][nf][0]), "+f"(acc[mf][nf][1]),
                                  "+f"(acc[mf][nf][2]), "+f"(acc[mf][nf][3])
                                : "r"(afr[mf][0]), "r"(afr[mf][1]), "r"(afr[mf][2]),
                                  "r"(afr[mf][3]), "r"(bfr[nf][0]), "r"(bfr[nf][1]));
                }
            }
        }
        __syncthreads();
    }

    // ---- epilogue
#pragma unroll
    for (int mf = 0; mf < 4; mf++)
#pragma unroll
        for (int nf = 0; nf < 4; nf++)
#pragma unroll
            for (int e = 0; e < 4; e++) {
                int m = m0 + wm * 64 + mf * 16 + g + (e >> 1) * 8;
                int c = j0 + wn * 32 + nf * 8 + 2 * tg + (e & 1);
                float v = acc[mf][nf][e];
                if (MODE == 1) {
                    ((float*)Cp)[(size_t)m * ldc + c] = v * dinv[m];
                } else if (MODE == 2) {
                    v = dinv[m] * (v + fil[m] * zaux[(size_t)m * ldb + c]) + bias[c];
                    if (relu) v = fmaxf(v, 0.f);
                    ((float*)Cp)[(size_t)m * ldc + c] = v;
                } else {
                    v = (m == c) ? 0.f
                                 : v + 2.f * __bfloat162float(adj[(size_t)m * lda + perm[c]]);
                    ((bf16*)Cp)[(size_t)m * ldc + c] = __float2bfloat16(v);
                }
            }
}

// ---------------- host orchestration ----------------
#define SYM(p, s)                     \
    do {                              \
        void* _t = nullptr;           \
        cudaGetSymbolAddress(&_t, s); \
        p = (decltype(p))_t;          \
    } while (0)

extern "C" void kernel_launch(void* const* d_in, const int* in_sizes, int n_in,
                              void* d_out, int out_size) {
    const float* x_in = (const float*)d_in[0];
    const int* ei     = (const int*)d_in[1];
    const float* w_d0 = (const float*)d_in[3];
    const float* b_d0 = (const float*)d_in[4];
    const float* w_d  = (const float*)d_in[5];
    const float* b_d  = (const float*)d_in[6];
    const float* p_at = (const float*)d_in[7];
    const float* w_u  = (const float*)d_in[8];
    const float* b_u  = (const float*)d_in[9];
    float* out = (float*)d_out;
    const int E = in_sizes[1] / 2;

    float* A0f;
    bf16 *A0, *A1, *A2, *A3, *AT0, *AT1, *AT2, *AT3, *Bp, *BpAT;
    float *X0, *X1, *X2, *Xc, *XW, *Xin;
    float *deg, *dinv, *fil, *sc, *pn;
    int* perm;
    SYM(A0f, g_A0f);
    SYM(A0, g_A0);   SYM(A1, g_A1);   SYM(A2, g_A2);   SYM(A3, g_A3);
    SYM(AT0, g_AT0); SYM(AT1, g_AT1); SYM(AT2, g_AT2); SYM(AT3, g_AT3);
    SYM(Bp, g_Bp);   SYM(BpAT, g_BpAT);
    SYM(X0, g_X0);   SYM(X1, g_X1);   SYM(X2, g_X2);
    SYM(Xc, g_Xc);   SYM(XW, g_XW);   SYM(Xin, g_Xin);
    SYM(deg, g_deg); SYM(dinv, g_dinv); SYM(fil, g_fil);
    SYM(sc, g_s);    SYM(pn, g_pn);   SYM(perm, g_perm);

    bf16* Alv[4] = {A0, A1, A2, A3};
    bf16* ATlv[4] = {AT0, AT1, AT2, AT3};
    float* Xs[3] = {X0, X1, X2};
    const int ns[4] = {4096, 2048, 1024, 512};

    // build dense A0 (fp32 staging) -> bf16 (exact integers) -> transpose
    zero_kernel<<<cdiv(N0 * N0, 256), 256>>>(A0f, (size_t)N0 * N0);
    edge_kernel<<<cdiv(E, 256), 256>>>(ei, E, A0f);
    f2bf_kernel<<<cdiv(N0 * N0, 256), 256>>>(A0f, A0, (size_t)N0 * N0);
    transpose_bf16<<<dim3(N0 / 32, N0 / 32), dim3(32, 8)>>>((uint16_t*)A0, (uint16_t*)AT0, N0);

    auto prep = [&](int lvl) {
        int n = ns[lvl];
        zero_kernel<<<cdiv(n, 256), 256>>>(deg + lvl * N0, n);
        colsum_bf16<<<dim3(n / 256, n / 256), 256>>>(Alv[lvl], n, deg + lvl * N0);
        finalize_deg_kernel<<<cdiv(n, 256), 256>>>(Alv[lvl], n, deg + lvl * N0,
                                                   dinv + lvl * N0, fil + lvl * N0);
    };
    auto gcn = [&](int lvl, const float* Xsrc, int Kin, const float* W,
                   const float* bias, float* Y, int relu) {
        int n = ns[lvl];
        // z = D^-1/2 * (X @ W)   (fp32 x fp32, 3-product split)
        mma_gemm<float, float, 1><<<dim3(CH / 128, n / 128), 256>>>(
            Xsrc, Kin, W, CH, XW, CH, Kin,
            dinv + lvl * N0, nullptr, nullptr, nullptr, nullptr, nullptr, 0);
        // Y = D^-1/2 * (A^T z + fill .* z) + b   (bf16-exact A x split z)
        mma_gemm<bf16, float, 2><<<dim3(CH / 128, n / 128), 256>>>(
            ATlv[lvl], n, XW, CH, Y, CH, n,
            dinv + lvl * N0, fil + lvl * N0, bias, XW, nullptr, nullptr, relu);
    };

    prep(0);
    gcn(0, x_in, 128, w_d0, b_d0, X0, 1);

    // ---- down path ----
    for (int i = 0; i < 3; i++) {
        int n = ns[i], k = ns[i + 1];
        int* pm = perm + i * 2048;
        const float* pvec = p_at + i * CH;

        pnorm_kernel<<<1, 256>>>(pvec, pn);
        score_kernel<<<n / 8, 256>>>(Xs[i], pvec, n, sc);
        sort_topk_kernel<<<1, 1024>>>(sc, n, k, pm);
        gather_x_kernel<<<cdiv(k * CH, 256), 256>>>(Xs[i], Xc, pm, sc, pn, k);

        // pooled augment: A_new[i,j] = sum_c A[pi,c]*AT[pj,c] + 2*A[pi,pj], zero diag
        gather_rows_bf16<<<cdiv(k * (n / 2), 256), 256>>>(Alv[i], n, pm, k, Bp);
        gather_rows_bf16<<<cdiv(k * (n / 2), 256), 256>>>(ATlv[i], n, pm, k, BpAT);
        mma_gemm<bf16, bf16, 3><<<dim3(k / 128, k / 128), 256>>>(
            Bp, n, BpAT, n, Alv[i + 1], k, n,
            nullptr, nullptr, nullptr, nullptr, Bp, pm, 0);
        transpose_bf16<<<dim3(k / 32, k / 32), dim3(32, 8)>>>(
            (uint16_t*)Alv[i + 1], (uint16_t*)ATlv[i + 1], k);

        prep(i + 1);
        if (i < 2)
            gcn(i + 1, Xc, CH, w_d + i * CH * CH, b_d + i * CH, Xs[i + 1], 1);
        else
            gcn(3, Xc, CH, w_d + 2 * CH * CH, b_d + 2 * CH, Xc, 1);
    }

    // ---- up path ----
    for (int i = 0; i < 3; i++) {
        int j = 2 - i;
        int nj = ns[j];
        int kj = ns[j + 1];
        copy_kernel<<<cdiv(nj * CH, 256), 256>>>(Xin, Xs[j], nj * CH);
        scatter_add_kernel<<<cdiv(kj * CH, 256), 256>>>(Xin, Xc, perm + j * 2048, kj);
        gcn(j, Xin, CH, w_u + i * CH * CH, b_u + i * CH, Xc, (i < 2) ? 1 : 0);
    }

    mean_kernel<<<1, 256>>>(Xc, N0, out);
}

// round 3
// speedup vs baseline: 4.3381x; 1.7578x over previous
#include <cuda_runtime.h>
#include <cuda_bf16.h>
#include <math.h>
#include <stdint.h>

#define N0 4096
#define CH 256

using bf16 = __nv_bfloat16;

// ---------------- scratch (static device globals; no allocations) ----------------
__device__ bf16  g_A0[(size_t)N0 * N0];
__device__ bf16  g_A1[2048 * 2048];
__device__ bf16  g_A2[1024 * 1024];
__device__ bf16  g_A3[512 * 512];
__device__ bf16  g_AT0[(size_t)N0 * N0];
__device__ bf16  g_AT1[2048 * 2048];
__device__ bf16  g_AT2[1024 * 1024];
__device__ bf16  g_AT3[512 * 512];
__device__ bf16  g_Bp[2048 * 4096];
__device__ bf16  g_BpAT[2048 * 4096];
__device__ float g_X0[N0 * CH];
__device__ float g_X1[2048 * CH];
__device__ float g_X2[1024 * CH];
__device__ float g_Xc[N0 * CH];
__device__ float g_Xin[N0 * CH];
__device__ bf16  g_Xhi[N0 * CH];
__device__ bf16  g_Xlo[N0 * CH];
__device__ bf16  g_Whi[CH * CH];
__device__ bf16  g_Wlo[CH * CH];
__device__ bf16  g_zhi[CH * N0];
__device__ bf16  g_zlo[CH * N0];
__device__ float g_Cpart[4 * N0 * CH];
__device__ float g_deg[4][N0];
__device__ float g_dinv[4][N0];
__device__ float g_fil[4][N0];
__device__ float g_s[N0];
__device__ float g_pn[1];
__device__ int   g_perm[3][2048];

static inline int cdiv(int a, int b) { return (a + b - 1) / b; }

// ---------------- small utility kernels ----------------
__global__ void copy_kernel(float* __restrict__ dst, const float* __restrict__ src, int n) {
    int i = blockIdx.x * blockDim.x + threadIdx.x;
    if (i < n) dst[i] = src[i];
}

// build A and A^T simultaneously with bf16 atomics (integer counts -> exact)
__global__ void edge_bf16(const int* __restrict__ ei, int E,
                          bf16* __restrict__ A, bf16* __restrict__ AT) {
    int i = blockIdx.x * blockDim.x + threadIdx.x;
    if (i >= E) return;
    int s = ei[i], d = ei[E + i];
    bf16 one = __float2bfloat16(1.0f);
    atomicAdd(A + (size_t)s * N0 + d, one);
    atomicAdd(AT + (size_t)d * N0 + s, one);
}

// 64x64 vectorized bf16 transpose
__global__ void transpose_bf16(const uint16_t* __restrict__ in, uint16_t* __restrict__ out, int n) {
    __shared__ uint16_t t[64][66];
    int bx = blockIdx.x * 64, by = blockIdx.y * 64;
    int tid = threadIdx.x;
#pragma unroll
    for (int i = 0; i < 8; i++) {
        int s = tid + i * 256;
        int r = s >> 5, c2 = s & 31;
        *(uint32_t*)&t[r][c2 * 2] = *(const uint32_t*)&in[(size_t)(by + r) * n + bx + c2 * 2];
    }
    __syncthreads();
#pragma unroll
    for (int i = 0; i < 8; i++) {
        int s = tid + i * 256;
        int r = s >> 5, c2 = s & 31;
        uint16_t a = t[c2 * 2][r];
        uint16_t b = t[c2 * 2 + 1][r];
        *(uint32_t*)&out[(size_t)(bx + r) * n + by + c2 * 2] = ((uint32_t)b << 16) | a;
    }
}

__global__ void colsum_bf16(const bf16* __restrict__ A, int n, float* __restrict__ deg) {
    int c = blockIdx.x * 256 + threadIdx.x;
    int r0 = blockIdx.y * 256;
    float sum = 0.f;
    for (int r = r0; r < r0 + 256; r++) sum += __bfloat162float(A[(size_t)r * n + c]);
    atomicAdd(&deg[c], sum);
}

__global__ void finalize_deg_kernel(const bf16* __restrict__ A, int n,
                                    const float* __restrict__ deg,
                                    float* __restrict__ dinv, float* __restrict__ fil) {
    int c = blockIdx.x * blockDim.x + threadIdx.x;
    if (c >= n) return;
    float f = (__bfloat162float(A[(size_t)c * n + c]) == 0.f) ? 2.f : 0.f;
    float d = deg[c] + f;
    dinv[c] = rsqrtf(d);
    fil[c] = f;
}

__global__ void pnorm_kernel(const float* __restrict__ p, float* __restrict__ pn) {
    __shared__ float red[8];
    int tid = threadIdx.x;
    float v = p[tid];
    v *= v;
#pragma unroll
    for (int o = 16; o; o >>= 1) v += __shfl_down_sync(0xffffffffu, v, o);
    if ((tid & 31) == 0) red[tid >> 5] = v;
    __syncthreads();
    if (tid < 8) {
        float a = red[tid];
#pragma unroll
        for (int o = 4; o; o >>= 1) a += __shfl_down_sync(0xffu, a, o);
        if (tid == 0) pn[0] = rsqrtf(a);
    }
}

__global__ void score_kernel(const float* __restrict__ x, const float* __restrict__ p,
                             int n, float* __restrict__ s) {
    int warp = (blockIdx.x * blockDim.x + threadIdx.x) >> 5;
    int lane = threadIdx.x & 31;
    if (warp >= n) return;
    const float* row = x + (size_t)warp * CH;
    float acc = 0.f;
#pragma unroll
    for (int q = 0; q < 8; q++) acc += row[lane + 32 * q] * p[lane + 32 * q];
#pragma unroll
    for (int o = 16; o; o >>= 1) acc += __shfl_down_sync(0xffffffffu, acc, o);
    if (lane == 0) s[warp] = acc;
}

__global__ void sort_topk_kernel(const float* __restrict__ s, int n, int k, int* __restrict__ perm) {
    __shared__ unsigned long long key[4096];
    int tid = threadIdx.x;
    for (int t = tid; t < 4096; t += blockDim.x) {
        unsigned long long kk;
        if (t < n) {
            unsigned int b = __float_as_uint(s[t]);
            unsigned int u = (b & 0x80000000u) ? ~b : (b | 0x80000000u);
            kk = ((unsigned long long)u << 32) | (unsigned int)(~(unsigned int)t);
        } else {
            kk = 0ull;
        }
        key[t] = kk;
    }
    __syncthreads();
    for (int k2 = 2; k2 <= 4096; k2 <<= 1) {
        for (int j = k2 >> 1; j >= 1; j >>= 1) {
            for (int t = tid; t < 4096; t += blockDim.x) {
                int ixj = t ^ j;
                if (ixj > t) {
                    bool desc = ((t & k2) == 0);
                    unsigned long long a = key[t], b = key[ixj];
                    bool sw = desc ? (a < b) : (a > b);
                    if (sw) { key[t] = b; key[ixj] = a; }
                }
            }
            __syncthreads();
        }
    }
    for (int t = tid; t < k; t += blockDim.x)
        perm[t] = (int)(~(unsigned int)(key[t] & 0xFFFFFFFFu));
}

__global__ void gather_x_kernel(const float* __restrict__ xold, float* __restrict__ xnew,
                                const int* __restrict__ perm, const float* __restrict__ s,
                                const float* __restrict__ pninv, int k) {
    int idx = blockIdx.x * blockDim.x + threadIdx.x;
    if (idx >= k * CH) return;
    int i = idx >> 8;
    int j = idx & 255;
    int pi = perm[i];
    float g = tanhf(s[pi] * pninv[0]);
    xnew[idx] = xold[(size_t)pi * CH + j] * g;
}

__global__ void gather_rows_bf16(const bf16* __restrict__ A, int n,
                                 const int* __restrict__ perm, int k, bf16* __restrict__ out) {
    int n2 = n >> 1;
    int idx = blockIdx.x * blockDim.x + threadIdx.x;
    if (idx >= k * n2) return;
    int i = idx / n2;
    int c2 = idx - i * n2;
    ((uint32_t*)out)[(size_t)i * n2 + c2] =
        ((const uint32_t*)(A + (size_t)perm[i] * n))[c2];
}

__global__ void scatter_add_kernel(float* __restrict__ Xin, const float* __restrict__ xcur,
                                   const int* __restrict__ perm, int k) {
    int idx = blockIdx.x * blockDim.x + threadIdx.x;
    if (idx >= k * CH) return;
    int i = idx >> 8;
    int j = idx & 255;
    Xin[(size_t)perm[i] * CH + j] += xcur[idx];
}

__global__ void mean_kernel(const float* __restrict__ x, int n, float* __restrict__ out) {
    int j = threadIdx.x;
    float s0 = 0.f, s1 = 0.f, s2 = 0.f, s3 = 0.f;
    for (int r = 0; r < n; r += 4) {
        s0 += x[(size_t)(r + 0) * CH + j];
        s1 += x[(size_t)(r + 1) * CH + j];
        s2 += x[(size_t)(r + 2) * CH + j];
        s3 += x[(size_t)(r + 3) * CH + j];
    }
    out[j] = (s0 + s1 + s2 + s3) / (float)n;
}

// fp32 -> (hi, lo) bf16 pair, layout preserved
__global__ void split_pair(const float* __restrict__ in, bf16* __restrict__ hi,
                           bf16* __restrict__ lo, int sz) {
    int i = blockIdx.x * blockDim.x + threadIdx.x;
    if (i >= sz) return;
    float v = in[i];
    bf16 h = __float2bfloat16(v);
    hi[i] = h;
    lo[i] = __float2bfloat16(v - __bfloat162float(h));
}

// W [K][256] fp32 -> Wt hi/lo [256][K] bf16
__global__ void splitT(const float* __restrict__ in, bf16* __restrict__ hi,
                       bf16* __restrict__ lo, int K) {
    int idx = blockIdx.x * blockDim.x + threadIdx.x;
    if (idx >= K * 256) return;
    int k = idx >> 8, c = idx & 255;
    float v = in[idx];
    bf16 h = __float2bfloat16(v);
    hi[(size_t)c * K + k] = h;
    lo[(size_t)c * K + k] = __float2bfloat16(v - __bfloat162float(h));
}

// GCN epilogue reduce: Y = dinv*(sum_s part + fil*z) + bias (+relu)
__global__ void reduce_gcn(const float* __restrict__ part, int S, int partStride, int M,
                           const bf16* __restrict__ zh, const bf16* __restrict__ zl,
                           const float* __restrict__ dinv, const float* __restrict__ fil,
                           const float* __restrict__ bias, float* __restrict__ Y, int relu) {
    int idx = blockIdx.x * blockDim.x + threadIdx.x;
    if (idx >= M * 256) return;
    int m = idx >> 8, c = idx & 255;
    float s = 0.f;
    for (int p = 0; p < S; p++) s += part[(size_t)p * partStride + idx];
    float z = __bfloat162float(zh[(size_t)c * M + m]) + __bfloat162float(zl[(size_t)c * M + m]);
    float v = dinv[m] * (s + fil[m] * z) + bias[c];
    if (relu) v = fmaxf(v, 0.f);
    Y[idx] = v;
}

// ---------------- cp.async double-buffered bf16 MMA GEMM, 128x128x32 ----------------
__device__ __forceinline__ void ld_tile(const bf16* __restrict__ src, int ld,
                                        int row0, int k0, uint16_t* dst, int tid) {
#pragma unroll
    for (int i = 0; i < 2; i++) {
        int s = tid + i * 256;
        int r = s >> 2, c8 = (s & 3) * 8;
        const bf16* g = src + (size_t)(row0 + r) * ld + k0 + c8;
        uint32_t sm = (uint32_t)__cvta_generic_to_shared(dst + r * 40 + c8);
        asm volatile("cp.async.ca.shared.global [%0], [%1], 16;\n" ::"r"(sm), "l"(g));
    }
}

// NPROD=1: (A0,B0)   NPROD=2: +(A0,B1)   NPROD=3: +(A1,B0)
// MODE=0: partial fp32 store at Cp + blockIdx.z*partStride
// MODE=1: z = dinv[m]*acc, write hi/lo bf16 TRANSPOSED: Cp/C2p[c*ldc + m]
// MODE=3: C = (m==c)?0 : acc + 2*adj[m*lda_adj + perm[c]]  (bf16 out, row-major)
template <int NPROD, int MODE>
__global__ void __launch_bounds__(256, 2) mma_gemm(
    const bf16* __restrict__ A0p, const bf16* __restrict__ A1p, int lda,
    const bf16* __restrict__ B0p, const bf16* __restrict__ B1p, int ldb,
    void* __restrict__ Cp, void* __restrict__ C2p, int ldc, int ksplit, int partStride,
    const float* __restrict__ dinv, const bf16* __restrict__ adj,
    const int* __restrict__ perm, int lda_adj) {
    constexpr int PA = (NPROD == 3) ? 2 : 1;
    constexpr int PB = (NPROD >= 2) ? 2 : 1;
    constexpr int TS = 128 * 40;  // u16 per tile

    extern __shared__ __align__(16) uint16_t sh[];

    const int tid = threadIdx.x;
    const int lane = tid & 31, warp = tid >> 5;
    const int g = lane >> 2, tg = lane & 3;
    const int wm = warp >> 2, wn = warp & 3;
    const int m0 = blockIdx.y * 128, j0 = blockIdx.x * 128;

    float acc[4][4][4];
#pragma unroll
    for (int a = 0; a < 4; a++)
#pragma unroll
        for (int b = 0; b < 4; b++)
#pragma unroll
            for (int e = 0; e < 4; e++) acc[a][b][e] = 0.f;

    auto load_stage = [&](int st, int k0) {
        ld_tile(A0p, lda, m0, k0, sh + st * TS, tid);
        if (PA == 2) ld_tile(A1p, lda, m0, k0, sh + (2 + st) * TS, tid);
        ld_tile(B0p, ldb, j0, k0, sh + (PA * 2 + st) * TS, tid);
        if (PB == 2) ld_tile(B1p, ldb, j0, k0, sh + (PA * 2 + 2 + st) * TS, tid);
        asm volatile("cp.async.commit_group;\n" ::);
    };

    const int kb = blockIdx.z * ksplit;
    const int nt = ksplit / 32;

    load_stage(0, kb);

    for (int it = 0; it < nt; it++) {
        if (it + 1 < nt) {
            load_stage((it + 1) & 1, kb + (it + 1) * 32);
            asm volatile("cp.async.wait_group 1;\n" ::);
        } else {
            asm volatile("cp.async.wait_group 0;\n" ::);
        }
        __syncthreads();
        const int st = it & 1;
        const uint16_t* As0 = sh + st * TS;
        const uint16_t* As1 = sh + (2 + st) * TS;
        const uint16_t* Bs0 = sh + (PA * 2 + st) * TS;
        const uint16_t* Bs1 = sh + (PA * 2 + 2 + st) * TS;

#pragma unroll
        for (int ks = 0; ks < 32; ks += 16) {
            auto do_prod = [&](const uint16_t* Asb, const uint16_t* Bsb) {
                uint32_t af[4][4], bfr[4][2];
                const int kc = ks + 2 * tg;
#pragma unroll
                for (int mf = 0; mf < 4; mf++) {
                    int m = wm * 64 + mf * 16 + g;
                    af[mf][0] = *(const uint32_t*)&Asb[m * 40 + kc];
                    af[mf][1] = *(const uint32_t*)&Asb[(m + 8) * 40 + kc];
                    af[mf][2] = *(const uint32_t*)&Asb[m * 40 + kc + 8];
                    af[mf][3] = *(const uint32_t*)&Asb[(m + 8) * 40 + kc + 8];
                }
#pragma unroll
                for (int nf = 0; nf < 4; nf++) {
                    int n = wn * 32 + nf * 8 + g;
                    bfr[nf][0] = *(const uint32_t*)&Bsb[n * 40 + kc];
                    bfr[nf][1] = *(const uint32_t*)&Bsb[n * 40 + kc + 8];
                }
#pragma unroll
                for (int mf = 0; mf < 4; mf++)
#pragma unroll
                    for (int nf = 0; nf < 4; nf++)
                        asm volatile(
                            "mma.sync.aligned.m16n8k16.row.col.f32.bf16.bf16.f32 "
                            "{%0,%1,%2,%3},{%4,%5,%6,%7},{%8,%9},{%0,%1,%2,%3};"
                            : "+f"(acc[mf][nf][0]), "+f"(acc[mf][nf][1]),
                              "+f"(acc[mf][nf][2]), "+f"(acc[mf][nf][3])
                            : "r"(af[mf][0]), "r"(af[mf][1]), "r"(af[mf][2]),
                              "r"(af[mf][3]), "r"(bfr[nf][0]), "r"(bfr[nf][1]));
            };
            do_prod(As0, Bs0);
            if (NPROD >= 2) do_prod(As0, Bs1);
            if (NPROD == 3) do_prod(As1, Bs0);
        }
        __syncthreads();
    }

    // ---- epilogue
#pragma unroll
    for (int mf = 0; mf < 4; mf++)
#pragma unroll
        for (int nf = 0; nf < 4; nf++)
#pragma unroll
            for (int e = 0; e < 4; e++) {
                int m = m0 + wm * 64 + mf * 16 + g + (e >> 1) * 8;
                int c = j0 + wn * 32 + nf * 8 + 2 * tg + (e & 1);
                float v = acc[mf][nf][e];
                if (MODE == 0) {
                    ((float*)Cp)[(size_t)blockIdx.z * partStride + (size_t)m * ldc + c] = v;
                } else if (MODE == 1) {
                    v *= dinv[m];
                    bf16 h = __float2bfloat16(v);
                    ((bf16*)Cp)[(size_t)c * ldc + m] = h;
                    ((bf16*)C2p)[(size_t)c * ldc + m] =
                        __float2bfloat16(v - __bfloat162float(h));
                } else {
                    v = (m == c) ? 0.f
                                 : v + 2.f * __bfloat162float(adj[(size_t)m * lda_adj + perm[c]]);
                    ((bf16*)Cp)[(size_t)m * ldc + c] = __float2bfloat16(v);
                }
            }
}

// ---------------- host orchestration ----------------
#define SYM(p, s)                     \
    do {                              \
        void* _t = nullptr;           \
        cudaGetSymbolAddress(&_t, s); \
        p = (decltype(p))_t;          \
    } while (0)

extern "C" void kernel_launch(void* const* d_in, const int* in_sizes, int n_in,
                              void* d_out, int out_size) {
    const float* x_in = (const float*)d_in[0];
    const int* ei     = (const int*)d_in[1];
    const float* w_d0 = (const float*)d_in[3];
    const float* b_d0 = (const float*)d_in[4];
    const float* w_d  = (const float*)d_in[5];
    const float* b_d  = (const float*)d_in[6];
    const float* p_at = (const float*)d_in[7];
    const float* w_u  = (const float*)d_in[8];
    const float* b_u  = (const float*)d_in[9];
    float* out = (float*)d_out;
    const int E = in_sizes[1] / 2;

    bf16 *A0, *A1, *A2, *A3, *AT0, *AT1, *AT2, *AT3, *Bp, *BpAT;
    bf16 *Xhi, *Xlo, *Whi, *Wlo, *zhi, *zlo;
    float *X0, *X1, *X2, *Xc, *Xin, *Cpart;
    float *deg, *dinv, *fil, *sc, *pn;
    int* perm;
    SYM(A0, g_A0);   SYM(A1, g_A1);   SYM(A2, g_A2);   SYM(A3, g_A3);
    SYM(AT0, g_AT0); SYM(AT1, g_AT1); SYM(AT2, g_AT2); SYM(AT3, g_AT3);
    SYM(Bp, g_Bp);   SYM(BpAT, g_BpAT);
    SYM(Xhi, g_Xhi); SYM(Xlo, g_Xlo); SYM(Whi, g_Whi); SYM(Wlo, g_Wlo);
    SYM(zhi, g_zhi); SYM(zlo, g_zlo);
    SYM(X0, g_X0);   SYM(X1, g_X1);   SYM(X2, g_X2);
    SYM(Xc, g_Xc);   SYM(Xin, g_Xin); SYM(Cpart, g_Cpart);
    SYM(deg, g_deg); SYM(dinv, g_dinv); SYM(fil, g_fil);
    SYM(sc, g_s);    SYM(pn, g_pn);   SYM(perm, g_perm);

    cudaFuncSetAttribute(mma_gemm<3, 1>, cudaFuncAttributeMaxDynamicSharedMemorySize, 81920);
    cudaFuncSetAttribute(mma_gemm<2, 0>, cudaFuncAttributeMaxDynamicSharedMemorySize, 61440);
    cudaFuncSetAttribute(mma_gemm<1, 3>, cudaFuncAttributeMaxDynamicSharedMemorySize, 40960);

    bf16* Alv[4] = {A0, A1, A2, A3};
    bf16* ATlv[4] = {AT0, AT1, AT2, AT3};
    float* Xs[3] = {X0, X1, X2};
    const int ns[4] = {4096, 2048, 1024, 512};

    // build dense bf16 A0 and AT0 directly
    cudaMemsetAsync(A0, 0, (size_t)N0 * N0 * sizeof(bf16));
    cudaMemsetAsync(AT0, 0, (size_t)N0 * N0 * sizeof(bf16));
    edge_bf16<<<cdiv(E, 256), 256>>>(ei, E, A0, AT0);

    auto prep = [&](int lvl) {
        int n = ns[lvl];
        cudaMemsetAsync(deg + lvl * N0, 0, n * sizeof(float));
        colsum_bf16<<<dim3(n / 256, n / 256), 256>>>(Alv[lvl], n, deg + lvl * N0);
        finalize_deg_kernel<<<cdiv(n, 256), 256>>>(Alv[lvl], n, deg + lvl * N0,
                                                   dinv + lvl * N0, fil + lvl * N0);
    };
    auto gcn = [&](int lvl, const float* Xsrc, int Kin, const float* W,
                   const float* bias, float* Y, int relu) {
        int n = ns[lvl];
        split_pair<<<cdiv(n * Kin, 256), 256>>>(Xsrc, Xhi, Xlo, n * Kin);
        splitT<<<cdiv(Kin * 256, 256), 256>>>(W, Whi, Wlo, Kin);
        // z^T (hi/lo) = (dinv * X @ W)^T    [256][n]
        mma_gemm<3, 1><<<dim3(2, n / 128), 256, 81920>>>(
            Xhi, Xlo, Kin, Whi, Wlo, Kin, zhi, zlo, n, Kin, 0,
            dinv + lvl * N0, nullptr, nullptr, 0);
        // partials of A^T z  (split-K = 4)
        mma_gemm<2, 0><<<dim3(2, n / 128, 4), 256, 61440>>>(
            ATlv[lvl], nullptr, n, zhi, zlo, n, Cpart, nullptr, 256, n / 4, n * 256,
            nullptr, nullptr, nullptr, 0);
        reduce_gcn<<<cdiv(n * 256, 256), 256>>>(Cpart, 4, n * 256, n, zhi, zlo,
                                                dinv + lvl * N0, fil + lvl * N0, bias, Y, relu);
    };

    prep(0);
    gcn(0, x_in, 128, w_d0, b_d0, X0, 1);

    // ---- down path ----
    for (int i = 0; i < 3; i++) {
        int n = ns[i], k = ns[i + 1];
        int* pm = perm + i * 2048;
        const float* pvec = p_at + i * CH;

        pnorm_kernel<<<1, 256>>>(pvec, pn);
        score_kernel<<<n / 8, 256>>>(Xs[i], pvec, n, sc);
        sort_topk_kernel<<<1, 1024>>>(sc, n, k, pm);
        gather_x_kernel<<<cdiv(k * CH, 256), 256>>>(Xs[i], Xc, pm, sc, pn, k);

        gather_rows_bf16<<<cdiv(k * (n / 2), 256), 256>>>(Alv[i], n, pm, k, Bp);
        gather_rows_bf16<<<cdiv(k * (n / 2), 256), 256>>>(ATlv[i], n, pm, k, BpAT);
        mma_gemm<1, 3><<<dim3(k / 128, k / 128), 256, 40960>>>(
            Bp, nullptr, n, BpAT, nullptr, n, Alv[i + 1], nullptr, k, n, 0,
            nullptr, Bp, pm, n);
        transpose_bf16<<<dim3(k / 64, k / 64), 256>>>(
            (uint16_t*)Alv[i + 1], (uint16_t*)ATlv[i + 1], k);

        prep(i + 1);
        if (i < 2)
            gcn(i + 1, Xc, CH, w_d + i * CH * CH, b_d + i * CH, Xs[i + 1], 1);
        else
            gcn(3, Xc, CH, w_d + 2 * CH * CH, b_d + 2 * CH, Xc, 1);
    }

    // ---- up path ----
    for (int i = 0; i < 3; i++) {
        int j = 2 - i;
        int nj = ns[j];
        int kj = ns[j + 1];
        copy_kernel<<<cdiv(nj * CH, 256), 256>>>(Xin, Xs[j], nj * CH);
        scatter_add_kernel<<<cdiv(kj * CH, 256), 256>>>(Xin, Xc, perm + j * 2048, kj);
        gcn(j, Xin, CH, w_u + i * CH * CH, b_u + i * CH, Xc, (i < 2) ? 1 : 0);
    }

    mean_kernel<<<1, 256>>>(Xc, N0, out);
}

// round 4
// speedup vs baseline: 6.2612x; 1.4433x over previous
#include <cuda_runtime.h>
#include <cuda_bf16.h>
#include <math.h>
#include <stdint.h>

#define N0 4096
#define CH 256
#define EMAX 131072

using bf16 = __nv_bfloat16;

// ---------------- scratch (static device globals; no allocations) ----------------
__device__ bf16  g_A1[2048 * 2048];
__device__ bf16  g_A2[1024 * 1024];
__device__ bf16  g_A3[512 * 512];
__device__ bf16  g_AT1[2048 * 2048];
__device__ bf16  g_AT2[1024 * 1024];
__device__ bf16  g_AT3[512 * 512];
__device__ bf16  g_Bp[1024 * 2048];
__device__ bf16  g_BpAT[1024 * 2048];
__device__ float g_A1f[2048 * 2048];
__device__ float g_X0[N0 * CH];
__device__ float g_X1[2048 * CH];
__device__ float g_X2[1024 * CH];
__device__ float g_Xc[N0 * CH];
__device__ float g_Xin[N0 * CH];
__device__ float g_z[N0 * CH];
__device__ bf16  g_Xhi[N0 * CH];
__device__ bf16  g_Xlo[N0 * CH];
__device__ bf16  g_Whi[CH * CH];
__device__ bf16  g_Wlo[CH * CH];
__device__ bf16  g_zhi[CH * N0];
__device__ bf16  g_zlo[CH * N0];
__device__ float g_Cpart[4 * N0 * CH];
__device__ float g_deg[4][N0];
__device__ float g_dinv[4][N0];
__device__ float g_fil[4][N0];
__device__ float g_s[N0];
__device__ float g_pn[1];
__device__ int   g_perm[3][2048];
// CSR
__device__ int g_rpi[N0 + 1], g_rpo[N0 + 1];
__device__ int g_cii[EMAX], g_cio[EMAX];
__device__ int g_curi[N0], g_curo[N0];
__device__ int g_ind[N0], g_outd[N0], g_selfc[N0];
__device__ int g_colmap[N0];

static inline int cdiv(int a, int b) { return (a + b - 1) / b; }

// ---------------- CSR build ----------------
__global__ void count_deg(const int* __restrict__ ei, int E, int* __restrict__ outd,
                          int* __restrict__ ind, int* __restrict__ selfc) {
    int i = blockIdx.x * blockDim.x + threadIdx.x;
    if (i >= E) return;
    int s = ei[i], d = ei[E + i];
    atomicAdd(outd + s, 1);
    atomicAdd(ind + d, 1);
    if (s == d) atomicAdd(selfc + s, 1);
}

__device__ void scan4096(const int* __restrict__ cnt, int* __restrict__ rp,
                         int* __restrict__ cur, int* loc) {
    int t = threadIdx.x;
    int base = t * 4;
    int v0 = cnt[base], v1 = cnt[base + 1], v2 = cnt[base + 2], v3 = cnt[base + 3];
    int s01 = v0 + v1;
    int s = s01 + v2 + v3;
    loc[t] = s;
    __syncthreads();
    for (int o = 1; o < 1024; o <<= 1) {
        int x = (t >= o) ? loc[t - o] : 0;
        __syncthreads();
        loc[t] += x;
        __syncthreads();
    }
    int excl = loc[t] - s;
    rp[base] = excl;           cur[base] = excl;
    rp[base + 1] = excl + v0;  cur[base + 1] = excl + v0;
    rp[base + 2] = excl + s01; cur[base + 2] = excl + s01;
    rp[base + 3] = excl + s01 + v2; cur[base + 3] = excl + s01 + v2;
    if (t == 1023) rp[4096] = excl + s;
}

__global__ void scan_build(const int* __restrict__ ind, const int* __restrict__ outd,
                           int* rpi, int* rpo, int* curi, int* curo) {
    __shared__ int loc[1024];
    scan4096(ind, rpi, curi, loc);
    __syncthreads();
    scan4096(outd, rpo, curo, loc);
}

__global__ void fill_csr(const int* __restrict__ ei, int E, int* curi, int* curo,
                         int* __restrict__ cii, int* __restrict__ cio) {
    int i = blockIdx.x * blockDim.x + threadIdx.x;
    if (i >= E) return;
    int s = ei[i], d = ei[E + i];
    int po = atomicAdd(curo + s, 1);
    cio[po] = d;
    int pi = atomicAdd(curi + d, 1);
    cii[pi] = s;
}

__global__ void lvl0_norm(const int* __restrict__ ind, const int* __restrict__ selfc,
                          float* __restrict__ dinv, float* __restrict__ fil) {
    int c = blockIdx.x * blockDim.x + threadIdx.x;
    if (c >= N0) return;
    float f = (selfc[c] == 0) ? 2.f : 0.f;
    fil[c] = f;
    dinv[c] = rsqrtf((float)ind[c] + f);
}

// sparse A^T z GCN: out[c] = dinv[c]*(sum_{(r->c)} z[r] + fil[c]*z[c]) + bias (+relu)
__global__ void spmv_gcn(const int* __restrict__ rp, const int* __restrict__ ci,
                         const float* __restrict__ z, const float* __restrict__ dinv,
                         const float* __restrict__ fil, const float* __restrict__ bias,
                         float* __restrict__ Y, int relu) {
    int c = blockIdx.x * 8 + (threadIdx.x >> 5);
    int lane = threadIdx.x & 31;
    float acc[8] = {0.f, 0.f, 0.f, 0.f, 0.f, 0.f, 0.f, 0.f};
    int e0 = rp[c], e1 = rp[c + 1];
    for (int e = e0; e < e1; e++) {
        int r = ci[e];
        const float4* zp = (const float4*)(z + (size_t)r * CH + lane * 8);
        float4 a = zp[0], b = zp[1];
        acc[0] += a.x; acc[1] += a.y; acc[2] += a.z; acc[3] += a.w;
        acc[4] += b.x; acc[5] += b.y; acc[6] += b.z; acc[7] += b.w;
    }
    const float4* zc = (const float4*)(z + (size_t)c * CH + lane * 8);
    float4 za = zc[0], zb = zc[1];
    float zv[8] = {za.x, za.y, za.z, za.w, zb.x, zb.y, zb.z, zb.w};
    float f = fil[c], dv = dinv[c];
    float* yo = Y + (size_t)c * CH + lane * 8;
#pragma unroll
    for (int q = 0; q < 8; q++) {
        float v = dv * (acc[q] + f * zv[q]) + bias[lane * 8 + q];
        if (relu) v = fmaxf(v, 0.f);
        yo[q] = v;
    }
}

__global__ void set_colmap(const int* __restrict__ pm, int k, int* __restrict__ colmap) {
    int j = blockIdx.x * blockDim.x + threadIdx.x;
    if (j < k) colmap[pm[j]] = j;
}

// sparse (A+I)^2 restricted to kept rows/cols: A1f[i][j] += 2*A[pi,*] + A^2[pi,*]
__global__ void sparse_augment(const int* __restrict__ pm, const int* __restrict__ colmap,
                               const int* __restrict__ rp, const int* __restrict__ ci,
                               float* __restrict__ A1f, int k) {
    int i = blockIdx.x;
    int pi = pm[i];
    int warp = threadIdx.x >> 5, lane = threadIdx.x & 31;
    float* row = A1f + (size_t)i * k;
    int b0 = rp[pi], b1 = rp[pi + 1];
    for (int e = b0 + threadIdx.x; e < b1; e += 256) {
        int j = colmap[ci[e]];
        if (j >= 0) atomicAdd(row + j, 2.f);
    }
    for (int e1 = b0 + warp; e1 < b1; e1 += 8) {
        int c = ci[e1];
        int c0 = rp[c], c1 = rp[c + 1];
        for (int e2 = c0 + lane; e2 < c1; e2 += 32) {
            int j = colmap[ci[e2]];
            if (j >= 0) atomicAdd(row + j, 1.f);
        }
    }
}

// fp32 -> bf16 A1 + AT1, zero diag, 64x64 tiles
__global__ void finalize_A1(const float* __restrict__ Af, bf16* __restrict__ A,
                            bf16* __restrict__ AT, int k) {
    __shared__ float t[64][65];
    int bx = blockIdx.x * 64, by = blockIdx.y * 64;
#pragma unroll
    for (int q = 0; q < 16; q++) {
        int s = q * 256 + threadIdx.x;
        int r = s >> 6, c = s & 63;
        float v = Af[(size_t)(by + r) * k + bx + c];
        if (by + r == bx + c) v = 0.f;
        A[(size_t)(by + r) * k + bx + c] = __float2bfloat16(v);
        t[r][c] = v;
    }
    __syncthreads();
#pragma unroll
    for (int q = 0; q < 16; q++) {
        int s = q * 256 + threadIdx.x;
        int r = s >> 6, c = s & 63;
        AT[(size_t)(bx + r) * k + by + c] = __float2bfloat16(t[c][r]);
    }
}

// ---------------- small utility kernels ----------------
__global__ void copy_kernel(float* __restrict__ dst, const float* __restrict__ src, int n) {
    int i = blockIdx.x * blockDim.x + threadIdx.x;
    if (i < n) dst[i] = src[i];
}

// 64x64 vectorized bf16 transpose
__global__ void transpose_bf16(const uint16_t* __restrict__ in, uint16_t* __restrict__ out, int n) {
    __shared__ uint16_t t[64][66];
    int bx = blockIdx.x * 64, by = blockIdx.y * 64;
    int tid = threadIdx.x;
#pragma unroll
    for (int i = 0; i < 8; i++) {
        int s = tid + i * 256;
        int r = s >> 5, c2 = s & 31;
        *(uint32_t*)&t[r][c2 * 2] = *(const uint32_t*)&in[(size_t)(by + r) * n + bx + c2 * 2];
    }
    __syncthreads();
#pragma unroll
    for (int i = 0; i < 8; i++) {
        int s = tid + i * 256;
        int r = s >> 5, c2 = s & 31;
        uint16_t a = t[c2 * 2][r];
        uint16_t b = t[c2 * 2 + 1][r];
        *(uint32_t*)&out[(size_t)(bx + r) * n + by + c2 * 2] = ((uint32_t)b << 16) | a;
    }
}

__global__ void colsum_bf16(const bf16* __restrict__ A, int n, float* __restrict__ deg) {
    int c = blockIdx.x * 256 + threadIdx.x;
    int r0 = blockIdx.y * 256;
    float sum = 0.f;
    for (int r = r0; r < r0 + 256; r++) sum += __bfloat162float(A[(size_t)r * n + c]);
    atomicAdd(&deg[c], sum);
}

__global__ void finalize_deg_kernel(const bf16* __restrict__ A, int n,
                                    const float* __restrict__ deg,
                                    float* __restrict__ dinv, float* __restrict__ fil) {
    int c = blockIdx.x * blockDim.x + threadIdx.x;
    if (c >= n) return;
    float f = (__bfloat162float(A[(size_t)c * n + c]) == 0.f) ? 2.f : 0.f;
    float d = deg[c] + f;
    dinv[c] = rsqrtf(d);
    fil[c] = f;
}

__global__ void pnorm_kernel(const float* __restrict__ p, float* __restrict__ pn) {
    __shared__ float red[8];
    int tid = threadIdx.x;
    float v = p[tid];
    v *= v;
#pragma unroll
    for (int o = 16; o; o >>= 1) v += __shfl_down_sync(0xffffffffu, v, o);
    if ((tid & 31) == 0) red[tid >> 5] = v;
    __syncthreads();
    if (tid < 8) {
        float a = red[tid];
#pragma unroll
        for (int o = 4; o; o >>= 1) a += __shfl_down_sync(0xffu, a, o);
        if (tid == 0) pn[0] = rsqrtf(a);
    }
}

__global__ void score_kernel(const float* __restrict__ x, const float* __restrict__ p,
                             int n, float* __restrict__ s) {
    int warp = (blockIdx.x * blockDim.x + threadIdx.x) >> 5;
    int lane = threadIdx.x & 31;
    if (warp >= n) return;
    const float* row = x + (size_t)warp * CH;
    float acc = 0.f;
#pragma unroll
    for (int q = 0; q < 8; q++) acc += row[lane + 32 * q] * p[lane + 32 * q];
#pragma unroll
    for (int o = 16; o; o >>= 1) acc += __shfl_down_sync(0xffffffffu, acc, o);
    if (lane == 0) s[warp] = acc;
}

__global__ void sort_topk_kernel(const float* __restrict__ s, int n, int k, int* __restrict__ perm) {
    __shared__ unsigned long long key[4096];
    int tid = threadIdx.x;
    for (int t = tid; t < 4096; t += blockDim.x) {
        unsigned long long kk;
        if (t < n) {
            unsigned int b = __float_as_uint(s[t]);
            unsigned int u = (b & 0x80000000u) ? ~b : (b | 0x80000000u);
            kk = ((unsigned long long)u << 32) | (unsigned int)(~(unsigned int)t);
        } else {
            kk = 0ull;
        }
        key[t] = kk;
    }
    __syncthreads();
    for (int k2 = 2; k2 <= 4096; k2 <<= 1) {
        for (int j = k2 >> 1; j >= 1; j >>= 1) {
            for (int t = tid; t < 4096; t += blockDim.x) {
                int ixj = t ^ j;
                if (ixj > t) {
                    bool desc = ((t & k2) == 0);
                    unsigned long long a = key[t], b = key[ixj];
                    bool sw = desc ? (a < b) : (a > b);
                    if (sw) { key[t] = b; key[ixj] = a; }
                }
            }
            __syncthreads();
        }
    }
    for (int t = tid; t < k; t += blockDim.x)
        perm[t] = (int)(~(unsigned int)(key[t] & 0xFFFFFFFFu));
}

__global__ void gather_x_kernel(const float* __restrict__ xold, float* __restrict__ xnew,
                                const int* __restrict__ perm, const float* __restrict__ s,
                                const float* __restrict__ pninv, int k) {
    int idx = blockIdx.x * blockDim.x + threadIdx.x;
    if (idx >= k * CH) return;
    int i = idx >> 8;
    int j = idx & 255;
    int pi = perm[i];
    float g = tanhf(s[pi] * pninv[0]);
    xnew[idx] = xold[(size_t)pi * CH + j] * g;
}

__global__ void gather_rows_bf16(const bf16* __restrict__ A, int n,
                                 const int* __restrict__ perm, int k, bf16* __restrict__ out) {
    int n2 = n >> 1;
    int idx = blockIdx.x * blockDim.x + threadIdx.x;
    if (idx >= k * n2) return;
    int i = idx / n2;
    int c2 = idx - i * n2;
    ((uint32_t*)out)[(size_t)i * n2 + c2] =
        ((const uint32_t*)(A + (size_t)perm[i] * n))[c2];
}

__global__ void scatter_add_kernel(float* __restrict__ Xin, const float* __restrict__ xcur,
                                   const int* __restrict__ perm, int k) {
    int idx = blockIdx.x * blockDim.x + threadIdx.x;
    if (idx >= k * CH) return;
    int i = idx >> 8;
    int j = idx & 255;
    Xin[(size_t)perm[i] * CH + j] += xcur[idx];
}

__global__ void mean_kernel(const float* __restrict__ x, int n, float* __restrict__ out) {
    int j = threadIdx.x;
    float s0 = 0.f, s1 = 0.f, s2 = 0.f, s3 = 0.f;
    for (int r = 0; r < n; r += 4) {
        s0 += x[(size_t)(r + 0) * CH + j];
        s1 += x[(size_t)(r + 1) * CH + j];
        s2 += x[(size_t)(r + 2) * CH + j];
        s3 += x[(size_t)(r + 3) * CH + j];
    }
    out[j] = (s0 + s1 + s2 + s3) / (float)n;
}

__global__ void split_pair(const float* __restrict__ in, bf16* __restrict__ hi,
                           bf16* __restrict__ lo, int sz) {
    int i = blockIdx.x * blockDim.x + threadIdx.x;
    if (i >= sz) return;
    float v = in[i];
    bf16 h = __float2bfloat16(v);
    hi[i] = h;
    lo[i] = __float2bfloat16(v - __bfloat162float(h));
}

__global__ void splitT(const float* __restrict__ in, bf16* __restrict__ hi,
                       bf16* __restrict__ lo, int K) {
    int idx = blockIdx.x * blockDim.x + threadIdx.x;
    if (idx >= K * 256) return;
    int k = idx >> 8, c = idx & 255;
    float v = in[idx];
    bf16 h = __float2bfloat16(v);
    hi[(size_t)c * K + k] = h;
    lo[(size_t)c * K + k] = __float2bfloat16(v - __bfloat162float(h));
}

__global__ void reduce_gcn(const float* __restrict__ part, int S, int partStride, int M,
                           const bf16* __restrict__ zh, const bf16* __restrict__ zl,
                           const float* __restrict__ dinv, const float* __restrict__ fil,
                           const float* __restrict__ bias, float* __restrict__ Y, int relu) {
    int idx = blockIdx.x * blockDim.x + threadIdx.x;
    if (idx >= M * 256) return;
    int m = idx >> 8, c = idx & 255;
    float s = 0.f;
    for (int p = 0; p < S; p++) s += part[(size_t)p * partStride + idx];
    float z = __bfloat162float(zh[(size_t)c * M + m]) + __bfloat162float(zl[(size_t)c * M + m]);
    float v = dinv[m] * (s + fil[m] * z) + bias[c];
    if (relu) v = fmaxf(v, 0.f);
    Y[idx] = v;
}

// ---------------- cp.async double-buffered bf16 MMA GEMM, 128x128x32 ----------------
__device__ __forceinline__ void ld_tile(const bf16* __restrict__ src, int ld,
                                        int row0, int k0, uint16_t* dst, int tid) {
#pragma unroll
    for (int i = 0; i < 2; i++) {
        int s = tid + i * 256;
        int r = s >> 2, c8 = (s & 3) * 8;
        const bf16* g = src + (size_t)(row0 + r) * ld + k0 + c8;
        uint32_t sm = (uint32_t)__cvta_generic_to_shared(dst + r * 40 + c8);
        asm volatile("cp.async.ca.shared.global [%0], [%1], 16;\n" ::"r"(sm), "l"(g));
    }
}

// MODE=0: partial fp32 at Cp + blockIdx.z*partStride
// MODE=1: z = dinv[m]*acc, hi/lo bf16 transposed
// MODE=2: z = dinv[m]*acc, fp32 row-major
// MODE=3: C = (m==c)?0 : acc + 2*adj[m*lda_adj + perm[c]]  (bf16 out)
template <int NPROD, int MODE>
__global__ void __launch_bounds__(256, 2) mma_gemm(
    const bf16* __restrict__ A0p, const bf16* __restrict__ A1p, int lda,
    const bf16* __restrict__ B0p, const bf16* __restrict__ B1p, int ldb,
    void* __restrict__ Cp, void* __restrict__ C2p, int ldc, int ksplit, int partStride,
    const float* __restrict__ dinv, const bf16* __restrict__ adj,
    const int* __restrict__ perm, int lda_adj) {
    constexpr int PA = (NPROD == 3) ? 2 : 1;
    constexpr int PB = (NPROD >= 2) ? 2 : 1;
    constexpr int TS = 128 * 40;

    extern __shared__ __align__(16) uint16_t sh[];

    const int tid = threadIdx.x;
    const int lane = tid & 31, warp = tid >> 5;
    const int g = lane >> 2, tg = lane & 3;
    const int wm = warp >> 2, wn = warp & 3;
    const int m0 = blockIdx.y * 128, j0 = blockIdx.x * 128;

    float acc[4][4][4];
#pragma unroll
    for (int a = 0; a < 4; a++)
#pragma unroll
        for (int b = 0; b < 4; b++)
#pragma unroll
            for (int e = 0; e < 4; e++) acc[a][b][e] = 0.f;

    auto load_stage = [&](int st, int k0) {
        ld_tile(A0p, lda, m0, k0, sh + st * TS, tid);
        if (PA == 2) ld_tile(A1p, lda, m0, k0, sh + (2 + st) * TS, tid);
        ld_tile(B0p, ldb, j0, k0, sh + (PA * 2 + st) * TS, tid);
        if (PB == 2) ld_tile(B1p, ldb, j0, k0, sh + (PA * 2 + 2 + st) * TS, tid);
        asm volatile("cp.async.commit_group;\n" ::);
    };

    const int kb = blockIdx.z * ksplit;
    const int nt = ksplit / 32;

    load_stage(0, kb);

    for (int it = 0; it < nt; it++) {
        if (it + 1 < nt) {
            load_stage((it + 1) & 1, kb + (it + 1) * 32);
            asm volatile("cp.async.wait_group 1;\n" ::);
        } else {
            asm volatile("cp.async.wait_group 0;\n" ::);
        }
        __syncthreads();
        const int st = it & 1;
        const uint16_t* As0 = sh + st * TS;
        const uint16_t* As1 = sh + (2 + st) * TS;
        const uint16_t* Bs0 = sh + (PA * 2 + st) * TS;
        const uint16_t* Bs1 = sh + (PA * 2 + 2 + st) * TS;

#pragma unroll
        for (int ks = 0; ks < 32; ks += 16) {
            auto do_prod = [&](const uint16_t* Asb, const uint16_t* Bsb) {
                uint32_t af[4][4], bfr[4][2];
                const int kc = ks + 2 * tg;
#pragma unroll
                for (int mf = 0; mf < 4; mf++) {
                    int m = wm * 64 + mf * 16 + g;
                    af[mf][0] = *(const uint32_t*)&Asb[m * 40 + kc];
                    af[mf][1] = *(const uint32_t*)&Asb[(m + 8) * 40 + kc];
                    af[mf][2] = *(const uint32_t*)&Asb[m * 40 + kc + 8];
                    af[mf][3] = *(const uint32_t*)&Asb[(m + 8) * 40 + kc + 8];
                }
#pragma unroll
                for (int nf = 0; nf < 4; nf++) {
                    int n = wn * 32 + nf * 8 + g;
                    bfr[nf][0] = *(const uint32_t*)&Bsb[n * 40 + kc];
                    bfr[nf][1] = *(const uint32_t*)&Bsb[n * 40 + kc + 8];
                }
#pragma unroll
                for (int mf = 0; mf < 4; mf++)
#pragma unroll
                    for (int nf = 0; nf < 4; nf++)
                        asm volatile(
                            "mma.sync.aligned.m16n8k16.row.col.f32.bf16.bf16.f32 "
                            "{%0,%1,%2,%3},{%4,%5,%6,%7},{%8,%9},{%0,%1,%2,%3};"
                            : "+f"(acc[mf][nf][0]), "+f"(acc[mf][nf][1]),
                              "+f"(acc[mf][nf][2]), "+f"(acc[mf][nf][3])
                            : "r"(af[mf][0]), "r"(af[mf][1]), "r"(af[mf][2]),
                              "r"(af[mf][3]), "r"(bfr[nf][0]), "r"(bfr[nf][1]));
            };
            do_prod(As0, Bs0);
            if (NPROD >= 2) do_prod(As0, Bs1);
            if (NPROD == 3) do_prod(As1, Bs0);
        }
        __syncthreads();
    }

#pragma unroll
    for (int mf = 0; mf < 4; mf++)
#pragma unroll
        for (int nf = 0; nf < 4; nf++)
#pragma unroll
            for (int e = 0; e < 4; e++) {
                int m = m0 + wm * 64 + mf * 16 + g + (e >> 1) * 8;
                int c = j0 + wn * 32 + nf * 8 + 2 * tg + (e & 1);
                float v = acc[mf][nf][e];
                if (MODE == 0) {
                    ((float*)Cp)[(size_t)blockIdx.z * partStride + (size_t)m * ldc + c] = v;
                } else if (MODE == 1) {
                    v *= dinv[m];
                    bf16 h = __float2bfloat16(v);
                    ((bf16*)Cp)[(size_t)c * ldc + m] = h;
                    ((bf16*)C2p)[(size_t)c * ldc + m] =
                        __float2bfloat16(v - __bfloat162float(h));
                } else if (MODE == 2) {
                    ((float*)Cp)[(size_t)m * ldc + c] = v * dinv[m];
                } else {
                    v = (m == c) ? 0.f
                                 : v + 2.f * __bfloat162float(adj[(size_t)m * lda_adj + perm[c]]);
                    ((bf16*)Cp)[(size_t)m * ldc + c] = __float2bfloat16(v);
                }
            }
}

// ---------------- host orchestration ----------------
#define SYM(p, s)                     \
    do {                              \
        void* _t = nullptr;           \
        cudaGetSymbolAddress(&_t, s); \
        p = (decltype(p))_t;          \
    } while (0)

extern "C" void kernel_launch(void* const* d_in, const int* in_sizes, int n_in,
                              void* d_out, int out_size) {
    const float* x_in = (const float*)d_in[0];
    const int* ei     = (const int*)d_in[1];
    const float* w_d0 = (const float*)d_in[3];
    const float* b_d0 = (const float*)d_in[4];
    const float* w_d  = (const float*)d_in[5];
    const float* b_d  = (const float*)d_in[6];
    const float* p_at = (const float*)d_in[7];
    const float* w_u  = (const float*)d_in[8];
    const float* b_u  = (const float*)d_in[9];
    float* out = (float*)d_out;
    const int E = in_sizes[1] / 2;

    bf16 *A1, *A2, *A3, *AT1, *AT2, *AT3, *Bp, *BpAT;
    bf16 *Xhi, *Xlo, *Whi, *Wlo, *zhi, *zlo;
    float *X0, *X1, *X2, *Xc, *Xin, *Cpart, *zf, *A1f;
    float *deg, *dinv, *fil, *sc, *pn;
    int *perm, *rpi, *rpo, *cii, *cio, *curi, *curo, *ind, *outd, *selfc, *colmap;
    SYM(A1, g_A1);   SYM(A2, g_A2);   SYM(A3, g_A3);
    SYM(AT1, g_AT1); SYM(AT2, g_AT2); SYM(AT3, g_AT3);
    SYM(Bp, g_Bp);   SYM(BpAT, g_BpAT);
    SYM(Xhi, g_Xhi); SYM(Xlo, g_Xlo); SYM(Whi, g_Whi); SYM(Wlo, g_Wlo);
    SYM(zhi, g_zhi); SYM(zlo, g_zlo);
    SYM(X0, g_X0);   SYM(X1, g_X1);   SYM(X2, g_X2);
    SYM(Xc, g_Xc);   SYM(Xin, g_Xin); SYM(Cpart, g_Cpart);
    SYM(zf, g_z);    SYM(A1f, g_A1f);
    SYM(deg, g_deg); SYM(dinv, g_dinv); SYM(fil, g_fil);
    SYM(sc, g_s);    SYM(pn, g_pn);   SYM(perm, g_perm);
    SYM(rpi, g_rpi); SYM(rpo, g_rpo); SYM(cii, g_cii); SYM(cio, g_cio);
    SYM(curi, g_curi); SYM(curo, g_curo);
    SYM(ind, g_ind); SYM(outd, g_outd); SYM(selfc, g_selfc); SYM(colmap, g_colmap);

    cudaFuncSetAttribute(mma_gemm<3, 1>, cudaFuncAttributeMaxDynamicSharedMemorySize, 81920);
    cudaFuncSetAttribute(mma_gemm<3, 2>, cudaFuncAttributeMaxDynamicSharedMemorySize, 81920);
    cudaFuncSetAttribute(mma_gemm<2, 0>, cudaFuncAttributeMaxDynamicSharedMemorySize, 61440);
    cudaFuncSetAttribute(mma_gemm<1, 3>, cudaFuncAttributeMaxDynamicSharedMemorySize, 40960);

    bf16* Alv[4] = {nullptr, A1, A2, A3};
    bf16* ATlv[4] = {nullptr, AT1, AT2, AT3};
    float* Xs[3] = {X0, X1, X2};
    const int ns[4] = {4096, 2048, 1024, 512};

    // ---- CSR build ----
    cudaMemsetAsync(ind, 0, N0 * sizeof(int));
    cudaMemsetAsync(outd, 0, N0 * sizeof(int));
    cudaMemsetAsync(selfc, 0, N0 * sizeof(int));
    count_deg<<<cdiv(E, 256), 256>>>(ei, E, outd, ind, selfc);
    scan_build<<<1, 1024>>>(ind, outd, rpi, rpo, curi, curo);
    fill_csr<<<cdiv(E, 256), 256>>>(ei, E, curi, curo, cii, cio);
    lvl0_norm<<<N0 / 256, 256>>>(ind, selfc, dinv, fil);

    auto prep = [&](int lvl) {
        int n = ns[lvl];
        cudaMemsetAsync(deg + lvl * N0, 0, n * sizeof(float));
        colsum_bf16<<<dim3(n / 256, n / 256), 256>>>(Alv[lvl], n, deg + lvl * N0);
        finalize_deg_kernel<<<cdiv(n, 256), 256>>>(Alv[lvl], n, deg + lvl * N0,
                                                   dinv + lvl * N0, fil + lvl * N0);
    };
    // lvl-0 sparse GCN
    auto gcn0 = [&](const float* Xsrc, int Kin, const float* W, const float* bias,
                    float* Y, int relu) {
        split_pair<<<cdiv(N0 * Kin, 256), 256>>>(Xsrc, Xhi, Xlo, N0 * Kin);
        splitT<<<cdiv(Kin * 256, 256), 256>>>(W, Whi, Wlo, Kin);
        mma_gemm<3, 2><<<dim3(2, N0 / 128), 256, 81920>>>(
            Xhi, Xlo, Kin, Whi, Wlo, Kin, zf, nullptr, 256, Kin, 0,
            dinv, nullptr, nullptr, 0);
        spmv_gcn<<<N0 / 8, 256>>>(rpi, cii, zf, dinv, fil, bias, Y, relu);
    };
    // dense GCN (levels 1..3)
    auto gcn = [&](int lvl, const float* Xsrc, const float* W, const float* bias,
                   float* Y, int relu) {
        int n = ns[lvl];
        split_pair<<<cdiv(n * CH, 256), 256>>>(Xsrc, Xhi, Xlo, n * CH);
        splitT<<<cdiv(CH * 256, 256), 256>>>(W, Whi, Wlo, CH);
        mma_gemm<3, 1><<<dim3(2, n / 128), 256, 81920>>>(
            Xhi, Xlo, CH, Whi, Wlo, CH, zhi, zlo, n, CH, 0,
            dinv + lvl * N0, nullptr, nullptr, 0);
        mma_gemm<2, 0><<<dim3(2, n / 128, 4), 256, 61440>>>(
            ATlv[lvl], nullptr, n, zhi, zlo, n, Cpart, nullptr, 256, n / 4, n * 256,
            nullptr, nullptr, nullptr, 0);
        reduce_gcn<<<cdiv(n * 256, 256), 256>>>(Cpart, 4, n * 256, n, zhi, zlo,
                                                dinv + lvl * N0, fil + lvl * N0, bias, Y, relu);
    };

    gcn0(x_in, 128, w_d0, b_d0, X0, 1);

    // ---- down path ----
    for (int i = 0; i < 3; i++) {
        int n = ns[i], k = ns[i + 1];
        int* pm = perm + i * 2048;
        const float* pvec = p_at + i * CH;

        pnorm_kernel<<<1, 256>>>(pvec, pn);
        score_kernel<<<n / 8, 256>>>(Xs[i], pvec, n, sc);
        sort_topk_kernel<<<1, 1024>>>(sc, n, k, pm);
        gather_x_kernel<<<cdiv(k * CH, 256), 256>>>(Xs[i], Xc, pm, sc, pn, k);

        if (i == 0) {
            // sparse augment at level 0
            cudaMemsetAsync(colmap, 0xFF, N0 * sizeof(int));
            set_colmap<<<cdiv(k, 256), 256>>>(pm, k, colmap);
            cudaMemsetAsync(A1f, 0, (size_t)k * k * sizeof(float));
            sparse_augment<<<k, 256>>>(pm, colmap, rpo, cio, A1f, k);
            finalize_A1<<<dim3(k / 64, k / 64), 256>>>(A1f, A1, AT1, k);
        } else {
            gather_rows_bf16<<<cdiv(k * (n / 2), 256), 256>>>(Alv[i], n, pm, k, Bp);
            gather_rows_bf16<<<cdiv(k * (n / 2), 256), 256>>>(ATlv[i], n, pm, k, BpAT);
            mma_gemm<1, 3><<<dim3(k / 128, k / 128), 256, 40960>>>(
                Bp, nullptr, n, BpAT, nullptr, n, Alv[i + 1], nullptr, k, n, 0,
                nullptr, Bp, pm, n);
            transpose_bf16<<<dim3(k / 64, k / 64), 256>>>(
                (uint16_t*)Alv[i + 1], (uint16_t*)ATlv[i + 1], k);
        }

        prep(i + 1);
        if (i < 2)
            gcn(i + 1, Xc, w_d + i * CH * CH, b_d + i * CH, Xs[i + 1], 1);
        else
            gcn(3, Xc, w_d + 2 * CH * CH, b_d + 2 * CH, Xc, 1);
    }

    // ---- up path ----
    for (int i = 0; i < 3; i++) {
        int j = 2 - i;
        int nj = ns[j];
        int kj = ns[j + 1];
        copy_kernel<<<cdiv(nj * CH, 256), 256>>>(Xin, Xs[j], nj * CH);
        scatter_add_kernel<<<cdiv(kj * CH, 256), 256>>>(Xin, Xc, perm + j * 2048, kj);
        if (j == 0)
            gcn0(Xin, CH, w_u + i * CH * CH, b_u + i * CH, Xc, 0);
        else
            gcn(j, Xin, w_u + i * CH * CH, b_u + i * CH, Xc, 1);
    }

    mean_kernel<<<1, 256>>>(Xc, N0, out);
}

// round 5
// speedup vs baseline: 9.5453x; 1.5245x over previous
#include <cuda_runtime.h>
#include <cuda_bf16.h>
#include <math.h>
#include <stdint.h>

#define N0 4096
#define CH 256
#define EMAX 131072

using bf16 = __nv_bfloat16;

// ---------------- scratch ----------------
__device__ bf16  g_A1[2048 * 2048];
__device__ bf16  g_A2[1024 * 1024];
__device__ bf16  g_A3[512 * 512];
__device__ bf16  g_AT1[2048 * 2048];
__device__ bf16  g_AT2[1024 * 1024];
__device__ bf16  g_AT3[512 * 512];
__device__ bf16  g_Bp[1024 * 2048];
__device__ bf16  g_BpAT[1024 * 2048];
__device__ float g_A1f[2048 * 2048];
__device__ float g_X0[N0 * CH];
__device__ float g_X1[2048 * CH];
__device__ float g_X2[1024 * CH];
__device__ float g_Xc[N0 * CH];
__device__ float g_z[N0 * CH];
__device__ bf16  g_Xhi[N0 * CH];
__device__ bf16  g_Xlo[N0 * CH];
__device__ bf16  g_Whi[CH * CH];
__device__ bf16  g_Wlo[CH * CH];
__device__ bf16  g_zhi[CH * N0];
__device__ bf16  g_zlo[CH * N0];
__device__ float g_Cpart[4 * N0 * CH];
__device__ float g_deg[4][N0];
__device__ float g_dinv[4][N0];
__device__ float g_fil[4][N0];
__device__ float g_s[N0];
__device__ float g_pn[1];
__device__ int   g_perm[3][2048];
__device__ int g_rpi[N0 + 1], g_rpo[N0 + 1];
__device__ int g_cii[EMAX], g_cio[EMAX];
__device__ int g_curi[N0], g_curo[N0];
__device__ int g_ind[N0], g_outd[N0], g_selfc[N0];
__device__ int g_colmap[N0];

static inline int cdiv(int a, int b) { return (a + b - 1) / b; }

// ---------------- CSR build ----------------
__global__ void count_deg(const int* __restrict__ ei, int E, int* __restrict__ outd,
                          int* __restrict__ ind, int* __restrict__ selfc) {
    int i = blockIdx.x * blockDim.x + threadIdx.x;
    if (i >= E) return;
    int s = ei[i], d = ei[E + i];
    atomicAdd(outd + s, 1);
    atomicAdd(ind + d, 1);
    if (s == d) atomicAdd(selfc + s, 1);
}

__device__ void scan4096(const int* __restrict__ cnt, int* __restrict__ rp,
                         int* __restrict__ cur, int* loc) {
    int t = threadIdx.x;
    int base = t * 4;
    int v0 = cnt[base], v1 = cnt[base + 1], v2 = cnt[base + 2], v3 = cnt[base + 3];
    int s01 = v0 + v1;
    int s = s01 + v2 + v3;
    loc[t] = s;
    __syncthreads();
    for (int o = 1; o < 1024; o <<= 1) {
        int x = (t >= o) ? loc[t - o] : 0;
        __syncthreads();
        loc[t] += x;
        __syncthreads();
    }
    int excl = loc[t] - s;
    rp[base] = excl;           cur[base] = excl;
    rp[base + 1] = excl + v0;  cur[base + 1] = excl + v0;
    rp[base + 2] = excl + s01; cur[base + 2] = excl + s01;
    rp[base + 3] = excl + s01 + v2; cur[base + 3] = excl + s01 + v2;
    if (t == 1023) rp[4096] = excl + s;
}

__global__ void scan_build(const int* __restrict__ ind, const int* __restrict__ outd,
                           int* rpi, int* rpo, int* curi, int* curo) {
    __shared__ int loc[1024];
    scan4096(ind, rpi, curi, loc);
    __syncthreads();
    scan4096(outd, rpo, curo, loc);
}

__global__ void fill_csr(const int* __restrict__ ei, int E, int* curi, int* curo,
                         int* __restrict__ cii, int* __restrict__ cio) {
    int i = blockIdx.x * blockDim.x + threadIdx.x;
    if (i >= E) return;
    int s = ei[i], d = ei[E + i];
    int po = atomicAdd(curo + s, 1);
    cio[po] = d;
    int pi = atomicAdd(curi + d, 1);
    cii[pi] = s;
}

__global__ void lvl0_norm(const int* __restrict__ ind, const int* __restrict__ selfc,
                          float* __restrict__ dinv, float* __restrict__ fil) {
    int c = blockIdx.x * blockDim.x + threadIdx.x;
    if (c >= N0) return;
    float f = (selfc[c] == 0) ? 2.f : 0.f;
    fil[c] = f;
    dinv[c] = rsqrtf((float)ind[c] + f);
}

__global__ void spmv_gcn(const int* __restrict__ rp, const int* __restrict__ ci,
                         const float* __restrict__ z, const float* __restrict__ dinv,
                         const float* __restrict__ fil, const float* __restrict__ bias,
                         float* __restrict__ Y, int relu) {
    int c = blockIdx.x * 8 + (threadIdx.x >> 5);
    int lane = threadIdx.x & 31;
    float acc[8] = {0.f, 0.f, 0.f, 0.f, 0.f, 0.f, 0.f, 0.f};
    int e0 = rp[c], e1 = rp[c + 1];
    for (int e = e0; e < e1; e++) {
        int r = ci[e];
        const float4* zp = (const float4*)(z + (size_t)r * CH + lane * 8);
        float4 a = zp[0], b = zp[1];
        acc[0] += a.x; acc[1] += a.y; acc[2] += a.z; acc[3] += a.w;
        acc[4] += b.x; acc[5] += b.y; acc[6] += b.z; acc[7] += b.w;
    }
    const float4* zc = (const float4*)(z + (size_t)c * CH + lane * 8);
    float4 za = zc[0], zb = zc[1];
    float zv[8] = {za.x, za.y, za.z, za.w, zb.x, zb.y, zb.z, zb.w};
    float f = fil[c], dv = dinv[c];
    float* yo = Y + (size_t)c * CH + lane * 8;
#pragma unroll
    for (int q = 0; q < 8; q++) {
        float v = dv * (acc[q] + f * zv[q]) + bias[lane * 8 + q];
        if (relu) v = fmaxf(v, 0.f);
        yo[q] = v;
    }
}

__global__ void set_colmap(const int* __restrict__ pm, int k, int* __restrict__ colmap) {
    int j = blockIdx.x * blockDim.x + threadIdx.x;
    if (j < k) colmap[pm[j]] = j;
}

__global__ void sparse_augment(const int* __restrict__ pm, const int* __restrict__ colmap,
                               const int* __restrict__ rp, const int* __restrict__ ci,
                               float* __restrict__ A1f, int k) {
    int i = blockIdx.x;
    int pi = pm[i];
    int warp = threadIdx.x >> 5, lane = threadIdx.x & 31;
    float* row = A1f + (size_t)i * k;
    int b0 = rp[pi], b1 = rp[pi + 1];
    for (int e = b0 + threadIdx.x; e < b1; e += 256) {
        int j = colmap[ci[e]];
        if (j >= 0) atomicAdd(row + j, 2.f);
    }
    for (int e1 = b0 + warp; e1 < b1; e1 += 8) {
        int c = ci[e1];
        int c0 = rp[c], c1 = rp[c + 1];
        for (int e2 = c0 + lane; e2 < c1; e2 += 32) {
            int j = colmap[ci[e2]];
            if (j >= 0) atomicAdd(row + j, 1.f);
        }
    }
}

// fp32 -> bf16 A + AT, zero diag, accumulate column sums (integer-exact atomics)
__global__ void finalize_A1(const float* __restrict__ Af, bf16* __restrict__ A,
                            bf16* __restrict__ AT, float* __restrict__ deg, int k) {
    __shared__ float t[64][65];
    int bx = blockIdx.x * 64, by = blockIdx.y * 64;
    int tid = threadIdx.x;
#pragma unroll
    for (int q = 0; q < 16; q++) {
        int s = q * 256 + tid;
        int r = s >> 6, c = s & 63;
        float v = Af[(size_t)(by + r) * k + bx + c];
        if (by + r == bx + c) v = 0.f;
        A[(size_t)(by + r) * k + bx + c] = __float2bfloat16(v);
        t[r][c] = v;
    }
    __syncthreads();
#pragma unroll
    for (int q = 0; q < 16; q++) {
        int s = q * 256 + tid;
        int r = s >> 6, c = s & 63;
        AT[(size_t)(bx + r) * k + by + c] = __float2bfloat16(t[c][r]);
    }
    if (tid < 64) {
        float s = 0.f;
#pragma unroll
        for (int r = 0; r < 64; r++) s += t[r][tid];
        atomicAdd(deg + bx + tid, s);
    }
}

// augment finalize for dense levels: v = Af + 2*Bp[m, pm[c]], zero diag, colsum
__global__ void finalize_aug(const float* __restrict__ Af, const bf16* __restrict__ Bp,
                             const int* __restrict__ pm, int k, int nprev,
                             bf16* __restrict__ A, bf16* __restrict__ AT,
                             float* __restrict__ deg) {
    __shared__ float t[64][65];
    __shared__ int pmv[64];
    int bx = blockIdx.x * 64, by = blockIdx.y * 64;
    int tid = threadIdx.x;
    if (tid < 64) pmv[tid] = pm[bx + tid];
    __syncthreads();
#pragma unroll
    for (int q = 0; q < 16; q++) {
        int s = q * 256 + tid;
        int r = s >> 6, c = s & 63;
        float v = Af[(size_t)(by + r) * k + bx + c] +
                  2.f * __bfloat162float(Bp[(size_t)(by + r) * nprev + pmv[c]]);
        if (by + r == bx + c) v = 0.f;
        A[(size_t)(by + r) * k + bx + c] = __float2bfloat16(v);
        t[r][c] = v;
    }
    __syncthreads();
#pragma unroll
    for (int q = 0; q < 16; q++) {
        int s = q * 256 + tid;
        int r = s >> 6, c = s & 63;
        AT[(size_t)(bx + r) * k + by + c] = __float2bfloat16(t[c][r]);
    }
    if (tid < 64) {
        float s = 0.f;
#pragma unroll
        for (int r = 0; r < 64; r++) s += t[r][tid];
        atomicAdd(deg + bx + tid, s);
    }
}

// augmented levels: diag always zero -> fill = 2
__global__ void deg_simple(const float* __restrict__ deg, int n,
                           float* __restrict__ dinv, float* __restrict__ fil) {
    int c = blockIdx.x * blockDim.x + threadIdx.x;
    if (c >= n) return;
    dinv[c] = rsqrtf(deg[c] + 2.f);
    fil[c] = 2.f;
}

// ---------------- small utility kernels ----------------
__global__ void pnorm_kernel(const float* __restrict__ p, float* __restrict__ pn) {
    __shared__ float red[8];
    int tid = threadIdx.x;
    float v = p[tid];
    v *= v;
#pragma unroll
    for (int o = 16; o; o >>= 1) v += __shfl_down_sync(0xffffffffu, v, o);
    if ((tid & 31) == 0) red[tid >> 5] = v;
    __syncthreads();
    if (tid < 8) {
        float a = red[tid];
#pragma unroll
        for (int o = 4; o; o >>= 1) a += __shfl_down_sync(0xffu, a, o);
        if (tid == 0) pn[0] = rsqrtf(a);
    }
}

__global__ void score_kernel(const float* __restrict__ x, const float* __restrict__ p,
                             int n, float* __restrict__ s) {
    int warp = (blockIdx.x * blockDim.x + threadIdx.x) >> 5;
    int lane = threadIdx.x & 31;
    if (warp >= n) return;
    const float* row = x + (size_t)warp * CH;
    float acc = 0.f;
#pragma unroll
    for (int q = 0; q < 8; q++) acc += row[lane + 32 * q] * p[lane + 32 * q];
#pragma unroll
    for (int o = 16; o; o >>= 1) acc += __shfl_down_sync(0xffffffffu, acc, o);
    if (lane == 0) s[warp] = acc;
}

template <int SZ>
__global__ void sort_topk_kernel(const float* __restrict__ s, int* __restrict__ perm) {
    __shared__ unsigned long long key[SZ];
    int tid = threadIdx.x;
    for (int t = tid; t < SZ; t += blockDim.x) {
        unsigned int b = __float_as_uint(s[t]);
        unsigned int u = (b & 0x80000000u) ? ~b : (b | 0x80000000u);
        key[t] = ((unsigned long long)u << 32) | (unsigned int)(~(unsigned int)t);
    }
    __syncthreads();
    for (int k2 = 2; k2 <= SZ; k2 <<= 1) {
        for (int j = k2 >> 1; j >= 1; j >>= 1) {
            for (int t = tid; t < SZ; t += blockDim.x) {
                int ixj = t ^ j;
                if (ixj > t) {
                    bool desc = ((t & k2) == 0);
                    unsigned long long a = key[t], b = key[ixj];
                    bool sw = desc ? (a < b) : (a > b);
                    if (sw) { key[t] = b; key[ixj] = a; }
                }
            }
            __syncthreads();
        }
    }
    for (int t = tid; t < SZ / 2; t += blockDim.x)
        perm[t] = (int)(~(unsigned int)(key[t] & 0xFFFFFFFFu));
}

// pooled gather: write gated x directly as (hi, lo) bf16 pair
__global__ void gather_x_kernel(const float* __restrict__ xold, bf16* __restrict__ hi,
                                bf16* __restrict__ lo, const int* __restrict__ perm,
                                const float* __restrict__ s, const float* __restrict__ pninv,
                                int k) {
    int idx = blockIdx.x * blockDim.x + threadIdx.x;
    if (idx >= k * CH) return;
    int i = idx >> 8;
    int j = idx & 255;
    int pi = perm[i];
    float g = tanhf(s[pi] * pninv[0]);
    float v = xold[(size_t)pi * CH + j] * g;
    bf16 h = __float2bfloat16(v);
    hi[idx] = h;
    lo[idx] = __float2bfloat16(v - __bfloat162float(h));
}

__global__ void gather_rows_bf16(const bf16* __restrict__ A, int n,
                                 const int* __restrict__ perm, int k, bf16* __restrict__ out) {
    int n2 = n >> 1;
    int idx = blockIdx.x * blockDim.x + threadIdx.x;
    if (idx >= k * n2) return;
    int i = idx / n2;
    int c2 = idx - i * n2;
    ((uint32_t*)out)[(size_t)i * n2 + c2] =
        ((const uint32_t*)(A + (size_t)perm[i] * n))[c2];
}

// up-path: Xin = res + unpool(xcur); emit split (hi, lo)
__global__ void unpool_split(const float* __restrict__ res, const float* __restrict__ xcur,
                             const int* __restrict__ inv, int n,
                             bf16* __restrict__ hi, bf16* __restrict__ lo) {
    int idx = blockIdx.x * blockDim.x + threadIdx.x;
    if (idx >= n * CH) return;
    int m = idx >> 8, c = idx & 255;
    float v = res[idx];
    int im = inv[m];
    if (im >= 0) v += xcur[(size_t)im * CH + c];
    bf16 h = __float2bfloat16(v);
    hi[idx] = h;
    lo[idx] = __float2bfloat16(v - __bfloat162float(h));
}

__global__ void mean_part(const float* __restrict__ x, float* __restrict__ part) {
    int b = blockIdx.x, j = threadIdx.x;
    float s = 0.f;
    for (int r = b * 128; r < b * 128 + 128; r++) s += x[(size_t)r * CH + j];
    part[b * 256 + j] = s;
}

__global__ void mean_final(const float* __restrict__ part, float* __restrict__ out) {
    int j = threadIdx.x;
    float s = 0.f;
#pragma unroll
    for (int b = 0; b < 32; b++) s += part[b * 256 + j];
    out[j] = s / (float)N0;
}

__global__ void split_pair(const float* __restrict__ in, bf16* __restrict__ hi,
                           bf16* __restrict__ lo, int sz) {
    int i = blockIdx.x * blockDim.x + threadIdx.x;
    if (i >= sz) return;
    float v = in[i];
    bf16 h = __float2bfloat16(v);
    hi[i] = h;
    lo[i] = __float2bfloat16(v - __bfloat162float(h));
}

__global__ void splitT(const float* __restrict__ in, bf16* __restrict__ hi,
                       bf16* __restrict__ lo, int K) {
    int idx = blockIdx.x * blockDim.x + threadIdx.x;
    if (idx >= K * 256) return;
    int k = idx >> 8, c = idx & 255;
    float v = in[idx];
    bf16 h = __float2bfloat16(v);
    hi[(size_t)c * K + k] = h;
    lo[(size_t)c * K + k] = __float2bfloat16(v - __bfloat162float(h));
}

// reduce XW partials -> z scaled by dinv, transposed hi/lo (smem tiled)
__global__ void reduce_z_tr(const float* __restrict__ part, int S, int ps, int n,
                            const float* __restrict__ dinv,
                            bf16* __restrict__ zhi, bf16* __restrict__ zlo) {
    __shared__ float t[32][33];
    int m0 = blockIdx.y * 32, c0 = blockIdx.x * 32;
    int mc = threadIdx.x & 31, r0 = threadIdx.x >> 5;
    for (int rr = r0; rr < 32; rr += 8) {
        float s = 0.f;
        for (int p = 0; p < S; p++) s += part[(size_t)p * ps + (size_t)(m0 + rr) * 256 + c0 + mc];
        t[rr][mc] = s * dinv[m0 + rr];
    }
    __syncthreads();
    for (int rr = r0; rr < 32; rr += 8) {
        float v = t[mc][rr];
        bf16 h = __float2bfloat16(v);
        zhi[(size_t)(c0 + rr) * n + m0 + mc] = h;
        zlo[(size_t)(c0 + rr) * n + m0 + mc] = __float2bfloat16(v - __bfloat162float(h));
    }
}

__global__ void reduce_z_f32(const float* __restrict__ part, int S, int ps, int n,
                             const float* __restrict__ dinv, float* __restrict__ z) {
    int idx = blockIdx.x * blockDim.x + threadIdx.x;
    if (idx >= n * 256) return;
    int m = idx >> 8;
    float s = 0.f;
    for (int p = 0; p < S; p++) s += part[(size_t)p * ps + idx];
    z[idx] = s * dinv[m];
}

__global__ void reduce_gcn(const float* __restrict__ part, int S, int partStride, int M,
                           const bf16* __restrict__ zh, const bf16* __restrict__ zl,
                           const float* __restrict__ dinv, const float* __restrict__ fil,
                           const float* __restrict__ bias, float* __restrict__ Y, int relu) {
    int idx = blockIdx.x * blockDim.x + threadIdx.x;
    if (idx >= M * 256) return;
    int m = idx >> 8, c = idx & 255;
    float s = 0.f;
    for (int p = 0; p < S; p++) s += part[(size_t)p * partStride + idx];
    float z = __bfloat162float(zh[(size_t)c * M + m]) + __bfloat162float(zl[(size_t)c * M + m]);
    float v = dinv[m] * (s + fil[m] * z) + bias[c];
    if (relu) v = fmaxf(v, 0.f);
    Y[idx] = v;
}

// ---------------- cp.async double-buffered bf16 MMA GEMM, 128x128x32 ----------------
__device__ __forceinline__ void ld_tile(const bf16* __restrict__ src, int ld,
                                        int row0, int k0, uint16_t* dst, int tid) {
#pragma unroll
    for (int i = 0; i < 2; i++) {
        int s = tid + i * 256;
        int r = s >> 2, c8 = (s & 3) * 8;
        const bf16* g = src + (size_t)(row0 + r) * ld + k0 + c8;
        uint32_t sm = (uint32_t)__cvta_generic_to_shared(dst + r * 40 + c8);
        asm volatile("cp.async.ca.shared.global [%0], [%1], 16;\n" ::"r"(sm), "l"(g));
    }
}

// MODE=0: partial fp32 at Cp + blockIdx.z*partStride
// MODE=4: atomicAdd fp32 partial into Cp (integer values -> exact, deterministic)
template <int NPROD, int MODE>
__global__ void __launch_bounds__(256, 2) mma_gemm(
    const bf16* __restrict__ A0p, const bf16* __restrict__ A1p, int lda,
    const bf16* __restrict__ B0p, const bf16* __restrict__ B1p, int ldb,
    void* __restrict__ Cp, int ldc, int ksplit, int partStride) {
    constexpr int PA = (NPROD == 3) ? 2 : 1;
    constexpr int PB = (NPROD >= 2) ? 2 : 1;
    constexpr int TS = 128 * 40;

    extern __shared__ __align__(16) uint16_t sh[];

    const int tid = threadIdx.x;
    const int lane = tid & 31, warp = tid >> 5;
    const int g = lane >> 2, tg = lane & 3;
    const int wm = warp >> 2, wn = warp & 3;
    const int m0 = blockIdx.y * 128, j0 = blockIdx.x * 128;

    float acc[4][4][4];
#pragma unroll
    for (int a = 0; a < 4; a++)
#pragma unroll
        for (int b = 0; b < 4; b++)
#pragma unroll
            for (int e = 0; e < 4; e++) acc[a][b][e] = 0.f;

    auto load_stage = [&](int st, int k0) {
        ld_tile(A0p, lda, m0, k0, sh + st * TS, tid);
        if (PA == 2) ld_tile(A1p, lda, m0, k0, sh + (2 + st) * TS, tid);
        ld_tile(B0p, ldb, j0, k0, sh + (PA * 2 + st) * TS, tid);
        if (PB == 2) ld_tile(B1p, ldb, j0, k0, sh + (PA * 2 + 2 + st) * TS, tid);
        asm volatile("cp.async.commit_group;\n" ::);
    };

    const int kb = blockIdx.z * ksplit;
    const int nt = ksplit / 32;

    load_stage(0, kb);

    for (int it = 0; it < nt; it++) {
        if (it + 1 < nt) {
            load_stage((it + 1) & 1, kb + (it + 1) * 32);
            asm volatile("cp.async.wait_group 1;\n" ::);
        } else {
            asm volatile("cp.async.wait_group 0;\n" ::);
        }
        __syncthreads();
        const int st = it & 1;
        const uint16_t* As0 = sh + st * TS;
        const uint16_t* As1 = sh + (2 + st) * TS;
        const uint16_t* Bs0 = sh + (PA * 2 + st) * TS;
        const uint16_t* Bs1 = sh + (PA * 2 + 2 + st) * TS;

#pragma unroll
        for (int ks = 0; ks < 32; ks += 16) {
            auto do_prod = [&](const uint16_t* Asb, const uint16_t* Bsb) {
                uint32_t af[4][4], bfr[4][2];
                const int kc = ks + 2 * tg;
#pragma unroll
                for (int mf = 0; mf < 4; mf++) {
                    int m = wm * 64 + mf * 16 + g;
                    af[mf][0] = *(const uint32_t*)&Asb[m * 40 + kc];
                    af[mf][1] = *(const uint32_t*)&Asb[(m + 8) * 40 + kc];
                    af[mf][2] = *(const uint32_t*)&Asb[m * 40 + kc + 8];
                    af[mf][3] = *(const uint32_t*)&Asb[(m + 8) * 40 + kc + 8];
                }
#pragma unroll
                for (int nf = 0; nf < 4; nf++) {
                    int n = wn * 32 + nf * 8 + g;
                    bfr[nf][0] = *(const uint32_t*)&Bsb[n * 40 + kc];
                    bfr[nf][1] = *(const uint32_t*)&Bsb[n * 40 + kc + 8];
                }
#pragma unroll
                for (int mf = 0; mf < 4; mf++)
#pragma unroll
                    for (int nf = 0; nf < 4; nf++)
                        asm volatile(
                            "mma.sync.aligned.m16n8k16.row.col.f32.bf16.bf16.f32 "
                            "{%0,%1,%2,%3},{%4,%5,%6,%7},{%8,%9},{%0,%1,%2,%3};"
                            : "+f"(acc[mf][nf][0]), "+f"(acc[mf][nf][1]),
                              "+f"(acc[mf][nf][2]), "+f"(acc[mf][nf][3])
                            : "r"(af[mf][0]), "r"(af[mf][1]), "r"(af[mf][2]),
                              "r"(af[mf][3]), "r"(bfr[nf][0]), "r"(bfr[nf][1]));
            };
            do_prod(As0, Bs0);
            if (NPROD >= 2) do_prod(As0, Bs1);
            if (NPROD == 3) do_prod(As1, Bs0);
        }
        __syncthreads();
    }

#pragma unroll
    for (int mf = 0; mf < 4; mf++)
#pragma unroll
        for (int nf = 0; nf < 4; nf++)
#pragma unroll
            for (int e = 0; e < 4; e++) {
                int m = m0 + wm * 64 + mf * 16 + g + (e >> 1) * 8;
                int c = j0 + wn * 32 + nf * 8 + 2 * tg + (e & 1);
                float v = acc[mf][nf][e];
                if (MODE == 0) {
                    ((float*)Cp)[(size_t)blockIdx.z * partStride + (size_t)m * ldc + c] = v;
                } else {
                    atomicAdd(&((float*)Cp)[(size_t)m * ldc + c], v);
                }
            }
}

// ---------------- host orchestration ----------------
#define SYM(p, s)                     \
    do {                              \
        void* _t = nullptr;           \
        cudaGetSymbolAddress(&_t, s); \
        p = (decltype(p))_t;          \
    } while (0)

extern "C" void kernel_launch(void* const* d_in, const int* in_sizes, int n_in,
                              void* d_out, int out_size) {
    const float* x_in = (const float*)d_in[0];
    const int* ei     = (const int*)d_in[1];
    const float* w_d0 = (const float*)d_in[3];
    const float* b_d0 = (const float*)d_in[4];
    const float* w_d  = (const float*)d_in[5];
    const float* b_d  = (const float*)d_in[6];
    const float* p_at = (const float*)d_in[7];
    const float* w_u  = (const float*)d_in[8];
    const float* b_u  = (const float*)d_in[9];
    float* out = (float*)d_out;
    const int E = in_sizes[1] / 2;

    bf16 *A1, *A2, *A3, *AT1, *AT2, *AT3, *Bp, *BpAT;
    bf16 *Xhi, *Xlo, *Whi, *Wlo, *zhi, *zlo;
    float *X0, *X1, *X2, *Xc, *Cpart, *zf, *A1f;
    float *deg, *dinv, *fil, *sc, *pn;
    int *perm, *rpi, *rpo, *cii, *cio, *curi, *curo, *ind, *outd, *selfc, *colmap;
    SYM(A1, g_A1);   SYM(A2, g_A2);   SYM(A3, g_A3);
    SYM(AT1, g_AT1); SYM(AT2, g_AT2); SYM(AT3, g_AT3);
    SYM(Bp, g_Bp);   SYM(BpAT, g_BpAT);
    SYM(Xhi, g_Xhi); SYM(Xlo, g_Xlo); SYM(Whi, g_Whi); SYM(Wlo, g_Wlo);
    SYM(zhi, g_zhi); SYM(zlo, g_zlo);
    SYM(X0, g_X0);   SYM(X1, g_X1);   SYM(X2, g_X2);
    SYM(Xc, g_Xc);   SYM(Cpart, g_Cpart);
    SYM(zf, g_z);    SYM(A1f, g_A1f);
    SYM(deg, g_deg); SYM(dinv, g_dinv); SYM(fil, g_fil);
    SYM(sc, g_s);    SYM(pn, g_pn);   SYM(perm, g_perm);
    SYM(rpi, g_rpi); SYM(rpo, g_rpo); SYM(cii, g_cii); SYM(cio, g_cio);
    SYM(curi, g_curi); SYM(curo, g_curo);
    SYM(ind, g_ind); SYM(outd, g_outd); SYM(selfc, g_selfc); SYM(colmap, g_colmap);

    cudaFuncSetAttribute(mma_gemm<3, 0>, cudaFuncAttributeMaxDynamicSharedMemorySize, 81920);
    cudaFuncSetAttribute(mma_gemm<2, 0>, cudaFuncAttributeMaxDynamicSharedMemorySize, 61440);
    cudaFuncSetAttribute(mma_gemm<1, 4>, cudaFuncAttributeMaxDynamicSharedMemorySize, 40960);

    bf16* Alv[4] = {nullptr, A1, A2, A3};
    bf16* ATlv[4] = {nullptr, AT1, AT2, AT3};
    float* Xs[3] = {X0, X1, X2};
    const int ns[4] = {4096, 2048, 1024, 512};

    // ---- CSR build ----
    cudaMemsetAsync(ind, 0, N0 * sizeof(int));
    cudaMemsetAsync(outd, 0, N0 * sizeof(int));
    cudaMemsetAsync(selfc, 0, N0 * sizeof(int));
    count_deg<<<cdiv(E, 256), 256>>>(ei, E, outd, ind, selfc);
    scan_build<<<1, 1024>>>(ind, outd, rpi, rpo, curi, curo);
    fill_csr<<<cdiv(E, 256), 256>>>(ei, E, curi, curo, cii, cio);
    lvl0_norm<<<N0 / 256, 256>>>(ind, selfc, dinv, fil);

    // lvl-0 sparse GCN; Xsrc==nullptr -> input already in Xhi/Xlo
    auto gcn0 = [&](const float* Xsrc, int Kin, const float* W, const float* bias,
                    float* Y, int relu) {
        if (Xsrc) split_pair<<<cdiv(N0 * Kin, 256), 256>>>(Xsrc, Xhi, Xlo, N0 * Kin);
        splitT<<<cdiv(Kin * 256, 256), 256>>>(W, Whi, Wlo, Kin);
        mma_gemm<3, 0><<<dim3(2, N0 / 128, 2), 256, 81920>>>(
            Xhi, Xlo, Kin, Whi, Wlo, Kin, Cpart, 256, Kin / 2, N0 * 256);
        reduce_z_f32<<<cdiv(N0 * 256, 256), 256>>>(Cpart, 2, N0 * 256, N0, dinv, zf);
        spmv_gcn<<<N0 / 8, 256>>>(rpi, cii, zf, dinv, fil, bias, Y, relu);
    };
    // dense GCN levels 1..3; input in Xhi/Xlo
    auto gcn = [&](int lvl, const float* W, const float* bias, float* Y, int relu) {
        int n = ns[lvl];
        splitT<<<cdiv(CH * 256, 256), 256>>>(W, Whi, Wlo, CH);
        mma_gemm<3, 0><<<dim3(2, n / 128, 4), 256, 81920>>>(
            Xhi, Xlo, CH, Whi, Wlo, CH, Cpart, 256, CH / 4, n * 256);
        reduce_z_tr<<<dim3(8, n / 32), 256>>>(Cpart, 4, n * 256, n, dinv + lvl * N0, zhi, zlo);
        mma_gemm<2, 0><<<dim3(2, n / 128, 4), 256, 61440>>>(
            ATlv[lvl], nullptr, n, zhi, zlo, n, Cpart, 256, n / 4, n * 256);
        reduce_gcn<<<cdiv(n * 256, 256), 256>>>(Cpart, 4, n * 256, n, zhi, zlo,
                                                dinv + lvl * N0, fil + lvl * N0, bias, Y, relu);
    };

    gcn0(x_in, 128, w_d0, b_d0, X0, 1);

    // ---- down path ----
    for (int i = 0; i < 3; i++) {
        int n = ns[i], k = ns[i + 1];
        int* pm = perm + i * 2048;
        const float* pvec = p_at + i * CH;

        pnorm_kernel<<<1, 256>>>(pvec, pn);
        score_kernel<<<n / 8, 256>>>(Xs[i], pvec, n, sc);
        if (i == 0) sort_topk_kernel<4096><<<1, 1024>>>(sc, pm);
        else if (i == 1) sort_topk_kernel<2048><<<1, 1024>>>(sc, pm);
        else sort_topk_kernel<1024><<<1, 1024>>>(sc, pm);
        gather_x_kernel<<<cdiv(k * CH, 256), 256>>>(Xs[i], Xhi, Xlo, pm, sc, pn, k);

        cudaMemsetAsync(deg + (i + 1) * N0, 0, k * sizeof(float));
        if (i == 0) {
            cudaMemsetAsync(colmap, 0xFF, n * sizeof(int));
            set_colmap<<<cdiv(k, 256), 256>>>(pm, k, colmap);
            cudaMemsetAsync(A1f, 0, (size_t)k * k * sizeof(float));
            sparse_augment<<<k, 256>>>(pm, colmap, rpo, cio, A1f, k);
            finalize_A1<<<dim3(k / 64, k / 64), 256>>>(A1f, A1, AT1, deg + N0, k);
        } else {
            gather_rows_bf16<<<cdiv(k * (n / 2), 256), 256>>>(Alv[i], n, pm, k, Bp);
            gather_rows_bf16<<<cdiv(k * (n / 2), 256), 256>>>(ATlv[i], n, pm, k, BpAT);
            cudaMemsetAsync(A1f, 0, (size_t)k * k * sizeof(float));
            mma_gemm<1, 4><<<dim3(k / 128, k / 128, 4), 256, 40960>>>(
                Bp, nullptr, n, BpAT, nullptr, n, A1f, k, n / 4, 0);
            finalize_aug<<<dim3(k / 64, k / 64), 256>>>(A1f, Bp, pm, k, n,
                                                        Alv[i + 1], ATlv[i + 1],
                                                        deg + (i + 1) * N0);
        }
        deg_simple<<<cdiv(k, 256), 256>>>(deg + (i + 1) * N0, k,
                                          dinv + (i + 1) * N0, fil + (i + 1) * N0);

        if (i < 2)
            gcn(i + 1, w_d + i * CH * CH, b_d + i * CH, Xs[i + 1], 1);
        else
            gcn(3, w_d + 2 * CH * CH, b_d + 2 * CH, Xc, 1);
    }

    // ---- up path ----
    for (int i = 0; i < 3; i++) {
        int j = 2 - i;
        int nj = ns[j];
        int kj = ns[j + 1];
        cudaMemsetAsync(colmap, 0xFF, nj * sizeof(int));
        set_colmap<<<cdiv(kj, 256), 256>>>(perm + j * 2048, kj, colmap);
        unpool_split<<<cdiv(nj * CH, 256), 256>>>(Xs[j], Xc, colmap, nj, Xhi, Xlo);
        if (j == 0)
            gcn0(nullptr, CH, w_u + i * CH * CH, b_u + i * CH, Xc, 0);
        else
            gcn(j, w_u + i * CH * CH, b_u + i * CH, Xc, 1);
    }

    mean_part<<<32, 256>>>(Xc, Cpart);
    mean_final<<<1, 256>>>(Cpart, out);
}

// round 6
// speedup vs baseline: 10.0647x; 1.0544x over previous
#include <cuda_runtime.h>
#include <cuda_bf16.h>
#include <math.h>
#include <stdint.h>

#define N0 4096
#define CH 256
#define EMAX 131072

using bf16 = __nv_bfloat16;

// ---------------- scratch ----------------
__device__ bf16  g_A1[2048 * 2048];
__device__ bf16  g_A2[1024 * 1024];
__device__ bf16  g_A3[512 * 512];
__device__ bf16  g_AT1[2048 * 2048];
__device__ bf16  g_AT2[1024 * 1024];
__device__ bf16  g_AT3[512 * 512];
__device__ float g_A1f[2048 * 2048];
__device__ float g_X0[N0 * CH];
__device__ float g_X1[2048 * CH];
__device__ float g_X2[1024 * CH];
__device__ float g_Xc[N0 * CH];
__device__ float g_z[N0 * CH];
__device__ bf16  g_Xhi[N0 * CH];
__device__ bf16  g_Xlo[N0 * CH];
__device__ bf16  g_Whi[CH * CH];
__device__ bf16  g_Wlo[CH * CH];
__device__ bf16  g_zhi[CH * N0];
__device__ bf16  g_zlo[CH * N0];
__device__ float g_Cpart[4 * N0 * CH];
__device__ float g_deg[4][N0];
__device__ float g_dinv0[N0];
__device__ float g_fil0[N0];
__device__ float g_s[N0];
__device__ float g_pn[1];
__device__ int   g_perm[3][2048];
__device__ int   g_colmap[3][N0];
__device__ int g_rpi[N0 + 1], g_rpo[N0 + 1];
__device__ int g_cii[EMAX], g_cio[EMAX];
__device__ int g_curi[N0], g_curo[N0];
__device__ int g_cnt[3 * N0];  // [ind | outd | selfc]

static inline int cdiv(int a, int b) { return (a + b - 1) / b; }

// ---------------- CSR build ----------------
__global__ void count_deg(const int* __restrict__ ei, int E, int* __restrict__ cnt) {
    int i = blockIdx.x * blockDim.x + threadIdx.x;
    if (i >= E) return;
    int s = ei[i], d = ei[E + i];
    atomicAdd(cnt + N0 + s, 1);   // outd
    atomicAdd(cnt + d, 1);        // ind
    if (s == d) atomicAdd(cnt + 2 * N0 + s, 1);
}

__device__ void scan4096(const int* __restrict__ cnt, int* __restrict__ rp,
                         int* __restrict__ cur, int* loc) {
    int t = threadIdx.x;
    int base = t * 4;
    int v0 = cnt[base], v1 = cnt[base + 1], v2 = cnt[base + 2], v3 = cnt[base + 3];
    int s01 = v0 + v1;
    int s = s01 + v2 + v3;
    loc[t] = s;
    __syncthreads();
    for (int o = 1; o < 1024; o <<= 1) {
        int x = (t >= o) ? loc[t - o] : 0;
        __syncthreads();
        loc[t] += x;
        __syncthreads();
    }
    int excl = loc[t] - s;
    rp[base] = excl;           cur[base] = excl;
    rp[base + 1] = excl + v0;  cur[base + 1] = excl + v0;
    rp[base + 2] = excl + s01; cur[base + 2] = excl + s01;
    rp[base + 3] = excl + s01 + v2; cur[base + 3] = excl + s01 + v2;
    if (t == 1023) rp[4096] = excl + s;
}

__global__ void scan_build(const int* __restrict__ cnt,
                           int* rpi, int* rpo, int* curi, int* curo) {
    __shared__ int loc[1024];
    scan4096(cnt, rpi, curi, loc);
    __syncthreads();
    scan4096(cnt + N0, rpo, curo, loc);
}

__global__ void fill_csr(const int* __restrict__ ei, int E, int* curi, int* curo,
                         int* __restrict__ cii, int* __restrict__ cio) {
    int i = blockIdx.x * blockDim.x + threadIdx.x;
    if (i >= E) return;
    int s = ei[i], d = ei[E + i];
    int po = atomicAdd(curo + s, 1);
    cio[po] = d;
    int pi = atomicAdd(curi + d, 1);
    cii[pi] = s;
}

__global__ void lvl0_norm(const int* __restrict__ cnt,
                          float* __restrict__ dinv, float* __restrict__ fil) {
    int c = blockIdx.x * blockDim.x + threadIdx.x;
    if (c >= N0) return;
    float f = (cnt[2 * N0 + c] == 0) ? 2.f : 0.f;
    fil[c] = f;
    dinv[c] = rsqrtf((float)cnt[c] + f);
}

__global__ void spmv_gcn(const int* __restrict__ rp, const int* __restrict__ ci,
                         const float* __restrict__ z, const float* __restrict__ dinv,
                         const float* __restrict__ fil, const float* __restrict__ bias,
                         float* __restrict__ Y, int relu) {
    int c = blockIdx.x * 8 + (threadIdx.x >> 5);
    int lane = threadIdx.x & 31;
    float acc[8] = {0.f, 0.f, 0.f, 0.f, 0.f, 0.f, 0.f, 0.f};
    int e0 = rp[c], e1 = rp[c + 1];
    for (int e = e0; e < e1; e++) {
        int r = ci[e];
        const float4* zp = (const float4*)(z + (size_t)r * CH + lane * 8);
        float4 a = zp[0], b = zp[1];
        acc[0] += a.x; acc[1] += a.y; acc[2] += a.z; acc[3] += a.w;
        acc[4] += b.x; acc[5] += b.y; acc[6] += b.z; acc[7] += b.w;
    }
    const float4* zc = (const float4*)(z + (size_t)c * CH + lane * 8);
    float4 za = zc[0], zb = zc[1];
    float zv[8] = {za.x, za.y, za.z, za.w, zb.x, zb.y, zb.z, zb.w};
    float f = fil[c], dv = dinv[c];
    float* yo = Y + (size_t)c * CH + lane * 8;
#pragma unroll
    for (int q = 0; q < 8; q++) {
        float v = dv * (acc[q] + f * zv[q]) + bias[lane * 8 + q];
        if (relu) v = fmaxf(v, 0.f);
        yo[q] = v;
    }
}

__global__ void sparse_augment(const int* __restrict__ pm, const int* __restrict__ colmap,
                               const int* __restrict__ rp, const int* __restrict__ ci,
                               float* __restrict__ A1f, int k) {
    int i = blockIdx.x;
    int pi = pm[i];
    int warp = threadIdx.x >> 5, lane = threadIdx.x & 31;
    float* row = A1f + (size_t)i * k;
    int b0 = rp[pi], b1 = rp[pi + 1];
    for (int e = b0 + threadIdx.x; e < b1; e += 256) {
        int j = colmap[ci[e]];
        if (j >= 0) atomicAdd(row + j, 2.f);
    }
    for (int e1 = b0 + warp; e1 < b1; e1 += 8) {
        int c = ci[e1];
        int c0 = rp[c], c1 = rp[c + 1];
        for (int e2 = c0 + lane; e2 < c1; e2 += 32) {
            int j = colmap[ci[e2]];
            if (j >= 0) atomicAdd(row + j, 1.f);
        }
    }
}

// fp32 -> bf16 A + AT, zero diag, colsum (integer-exact atomics)
__global__ void finalize_A1(const float* __restrict__ Af, bf16* __restrict__ A,
                            bf16* __restrict__ AT, float* __restrict__ deg, int k) {
    __shared__ float t[64][65];
    int bx = blockIdx.x * 64, by = blockIdx.y * 64;
    int tid = threadIdx.x;
#pragma unroll
    for (int q = 0; q < 16; q++) {
        int s = q * 256 + tid;
        int r = s >> 6, c = s & 63;
        float v = Af[(size_t)(by + r) * k + bx + c];
        if (by + r == bx + c) v = 0.f;
        A[(size_t)(by + r) * k + bx + c] = __float2bfloat16(v);
        t[r][c] = v;
    }
    __syncthreads();
#pragma unroll
    for (int q = 0; q < 16; q++) {
        int s = q * 256 + tid;
        int r = s >> 6, c = s & 63;
        AT[(size_t)(bx + r) * k + by + c] = __float2bfloat16(t[c][r]);
    }
    if (tid < 64) {
        float s = 0.f;
#pragma unroll
        for (int r = 0; r < 64; r++) s += t[r][tid];
        atomicAdd(deg + bx + tid, s);
    }
}

// v = Af + 2*Aprev[pm[r], pm[c]], zero diag, colsum, emit A + AT
__global__ void finalize_aug(const float* __restrict__ Af, const bf16* __restrict__ Aprev,
                             const int* __restrict__ pm, int k, int nprev,
                             bf16* __restrict__ A, bf16* __restrict__ AT,
                             float* __restrict__ deg) {
    __shared__ float t[64][65];
    __shared__ int pmc[64], pmr[64];
    int bx = blockIdx.x * 64, by = blockIdx.y * 64;
    int tid = threadIdx.x;
    if (tid < 64) pmc[tid] = pm[bx + tid];
    else if (tid < 128) pmr[tid - 64] = pm[by + tid - 64];
    __syncthreads();
#pragma unroll
    for (int q = 0; q < 16; q++) {
        int s = q * 256 + tid;
        int r = s >> 6, c = s & 63;
        float v = Af[(size_t)(by + r) * k + bx + c] +
                  2.f * __bfloat162float(Aprev[(size_t)pmr[r] * nprev + pmc[c]]);
        if (by + r == bx + c) v = 0.f;
        A[(size_t)(by + r) * k + bx + c] = __float2bfloat16(v);
        t[r][c] = v;
    }
    __syncthreads();
#pragma unroll
    for (int q = 0; q < 16; q++) {
        int s = q * 256 + tid;
        int r = s >> 6, c = s & 63;
        AT[(size_t)(bx + r) * k + by + c] = __float2bfloat16(t[c][r]);
    }
    if (tid < 64) {
        float s = 0.f;
#pragma unroll
        for (int r = 0; r < 64; r++) s += t[r][tid];
        atomicAdd(deg + bx + tid, s);
    }
}

// ---------------- score (+ fused pnorm in last block) ----------------
__global__ void score_kernel(const float* __restrict__ x, const float* __restrict__ p,
                             int n, float* __restrict__ s, float* __restrict__ pn) {
    if (blockIdx.x == gridDim.x - 1) {
        __shared__ float red[8];
        int tid = threadIdx.x;
        float v = p[tid];
        v *= v;
#pragma unroll
        for (int o = 16; o; o >>= 1) v += __shfl_down_sync(0xffffffffu, v, o);
        if ((tid & 31) == 0) red[tid >> 5] = v;
        __syncthreads();
        if (tid < 8) {
            float a = red[tid];
#pragma unroll
            for (int o = 4; o; o >>= 1) a += __shfl_down_sync(0xffu, a, o);
            if (tid == 0) pn[0] = rsqrtf(a);
        }
        return;
    }
    int warp = (blockIdx.x * blockDim.x + threadIdx.x) >> 5;
    int lane = threadIdx.x & 31;
    if (warp >= n) return;
    const float* row = x + (size_t)warp * CH;
    float acc = 0.f;
#pragma unroll
    for (int q = 0; q < 8; q++) acc += row[lane + 32 * q] * p[lane + 32 * q];
#pragma unroll
    for (int o = 16; o; o >>= 1) acc += __shfl_down_sync(0xffffffffu, acc, o);
    if (lane == 0) s[warp] = acc;
}

template <int SZ>
__global__ void sort_topk_kernel(const float* __restrict__ s, int* __restrict__ perm,
                                 int* __restrict__ colmap) {
    __shared__ unsigned long long key[SZ];
    int tid = threadIdx.x;
    for (int t = tid; t < SZ; t += blockDim.x) {
        unsigned int b = __float_as_uint(s[t]);
        unsigned int u = (b & 0x80000000u) ? ~b : (b | 0x80000000u);
        key[t] = ((unsigned long long)u << 32) | (unsigned int)(~(unsigned int)t);
    }
    __syncthreads();
    for (int k2 = 2; k2 <= SZ; k2 <<= 1) {
        for (int j = k2 >> 1; j >= 1; j >>= 1) {
            for (int t = tid; t < SZ; t += blockDim.x) {
                int ixj = t ^ j;
                if (ixj > t) {
                    bool desc = ((t & k2) == 0);
                    unsigned long long a = key[t], b = key[ixj];
                    bool sw = desc ? (a < b) : (a > b);
                    if (sw) { key[t] = b; key[ixj] = a; }
                }
            }
            __syncthreads();
        }
    }
    for (int t = tid; t < SZ / 2; t += blockDim.x) {
        int idx = (int)(~(unsigned int)(key[t] & 0xFFFFFFFFu));
        perm[t] = idx;
        colmap[idx] = t;
    }
}

__global__ void gather_x_kernel(const float* __restrict__ xold, bf16* __restrict__ hi,
                                bf16* __restrict__ lo, const int* __restrict__ perm,
                                const float* __restrict__ s, const float* __restrict__ pninv,
                                int k) {
    int idx = blockIdx.x * blockDim.x + threadIdx.x;
    if (idx >= k * CH) return;
    int i = idx >> 8;
    int j = idx & 255;
    int pi = perm[i];
    float g = tanhf(s[pi] * pninv[0]);
    float v = xold[(size_t)pi * CH + j] * g;
    bf16 h = __float2bfloat16(v);
    hi[idx] = h;
    lo[idx] = __float2bfloat16(v - __bfloat162float(h));
}

__global__ void unpool_split(const float* __restrict__ res, const float* __restrict__ xcur,
                             const int* __restrict__ inv, int n,
                             bf16* __restrict__ hi, bf16* __restrict__ lo) {
    int idx = blockIdx.x * blockDim.x + threadIdx.x;
    if (idx >= n * CH) return;
    int m = idx >> 8, c = idx & 255;
    float v = res[idx];
    int im = inv[m];
    if (im >= 0) v += xcur[(size_t)im * CH + c];
    bf16 h = __float2bfloat16(v);
    hi[idx] = h;
    lo[idx] = __float2bfloat16(v - __bfloat162float(h));
}

__global__ void mean_part(const float* __restrict__ x, float* __restrict__ part) {
    int b = blockIdx.x, j = threadIdx.x;
    float s = 0.f;
    for (int r = b * 128; r < b * 128 + 128; r++) s += x[(size_t)r * CH + j];
    part[b * 256 + j] = s;
}

__global__ void mean_final(const float* __restrict__ part, float* __restrict__ out) {
    int j = threadIdx.x;
    float s = 0.f;
#pragma unroll
    for (int b = 0; b < 32; b++) s += part[b * 256 + j];
    out[j] = s / (float)N0;
}

__global__ void split_pair(const float* __restrict__ in, bf16* __restrict__ hi,
                           bf16* __restrict__ lo, int sz) {
    int i = blockIdx.x * blockDim.x + threadIdx.x;
    if (i >= sz) return;
    float v = in[i];
    bf16 h = __float2bfloat16(v);
    hi[i] = h;
    lo[i] = __float2bfloat16(v - __bfloat162float(h));
}

__global__ void splitT(const float* __restrict__ in, bf16* __restrict__ hi,
                       bf16* __restrict__ lo, int K) {
    int idx = blockIdx.x * blockDim.x + threadIdx.x;
    if (idx >= K * 256) return;
    int k = idx >> 8, c = idx & 255;
    float v = in[idx];
    bf16 h = __float2bfloat16(v);
    hi[(size_t)c * K + k] = h;
    lo[(size_t)c * K + k] = __float2bfloat16(v - __bfloat162float(h));
}

// GCN final reduce over split-K partials; augmented levels: fill=2, dinv=rsqrt(deg+2)
__global__ void reduce_gcn(const float* __restrict__ part, int S, int partStride, int M,
                           const bf16* __restrict__ zh, const bf16* __restrict__ zl,
                           const float* __restrict__ deg,
                           const float* __restrict__ bias, float* __restrict__ Y, int relu) {
    int idx = blockIdx.x * blockDim.x + threadIdx.x;
    if (idx >= M * 256) return;
    int m = idx >> 8, c = idx & 255;
    float s = 0.f;
    for (int p = 0; p < S; p++) s += part[(size_t)p * partStride + idx];
    float z = __bfloat162float(zh[(size_t)c * M + m]) + __bfloat162float(zl[(size_t)c * M + m]);
    float dv = rsqrtf(deg[m] + 2.f);
    float v = dv * (s + 2.f * z) + bias[c];
    if (relu) v = fmaxf(v, 0.f);
    Y[idx] = v;
}

// ---------------- cp.async double-buffered bf16 MMA GEMM, 128x128x32 ----------------
template <int G>
__device__ __forceinline__ void ld_tile(const bf16* __restrict__ src, int ld,
                                        int row0, int k0, uint16_t* dst, int tid,
                                        const int* __restrict__ pm) {
#pragma unroll
    for (int i = 0; i < 2; i++) {
        int s = tid + i * 256;
        int r = s >> 2, c8 = (s & 3) * 8;
        int row = row0 + r;
        if (G) row = pm[row];
        const bf16* g = src + (size_t)row * ld + k0 + c8;
        uint32_t sm = (uint32_t)__cvta_generic_to_shared(dst + r * 40 + c8);
        asm volatile("cp.async.ca.shared.global [%0], [%1], 16;\n" ::"r"(sm), "l"(g));
    }
}

// MODE=0: fp32 partial at Cp + blockIdx.z*partStride (ldc=256)
// MODE=1: z = rsqrt(scl[m]+2)*acc, hi/lo bf16 transposed at [c*ldc+m]
// MODE=2: z = scl[m]*acc, fp32 row-major
// MODE=4: atomicAdd fp32 into Cp (integer values -> exact)
// G=1: A and B tile rows indexed through pm
template <int NPROD, int MODE, int G>
__global__ void __launch_bounds__(256, 2) mma_gemm(
    const bf16* __restrict__ A0p, const bf16* __restrict__ A1p, int lda,
    const bf16* __restrict__ B0p, const bf16* __restrict__ B1p, int ldb,
    void* __restrict__ Cp, void* __restrict__ C2p, int ldc, int ksplit, int partStride,
    const float* __restrict__ scl, const int* __restrict__ pm) {
    constexpr int PA = (NPROD == 3) ? 2 : 1;
    constexpr int PB = (NPROD >= 2) ? 2 : 1;
    constexpr int TS = 128 * 40;

    extern __shared__ __align__(16) uint16_t sh[];

    const int tid = threadIdx.x;
    const int lane = tid & 31, warp = tid >> 5;
    const int g = lane >> 2, tg = lane & 3;
    const int wm = warp >> 2, wn = warp & 3;
    const int m0 = blockIdx.y * 128, j0 = blockIdx.x * 128;

    float acc[4][4][4];
#pragma unroll
    for (int a = 0; a < 4; a++)
#pragma unroll
        for (int b = 0; b < 4; b++)
#pragma unroll
            for (int e = 0; e < 4; e++) acc[a][b][e] = 0.f;

    auto load_stage = [&](int st, int k0) {
        ld_tile<G>(A0p, lda, m0, k0, sh + st * TS, tid, pm);
        if (PA == 2) ld_tile<G>(A1p, lda, m0, k0, sh + (2 + st) * TS, tid, pm);
        ld_tile<G>(B0p, ldb, j0, k0, sh + (PA * 2 + st) * TS, tid, pm);
        if (PB == 2) ld_tile<G>(B1p, ldb, j0, k0, sh + (PA * 2 + 2 + st) * TS, tid, pm);
        asm volatile("cp.async.commit_group;\n" ::);
    };

    const int kb = blockIdx.z * ksplit;
    const int nt = ksplit / 32;

    load_stage(0, kb);

    for (int it = 0; it < nt; it++) {
        if (it + 1 < nt) {
            load_stage((it + 1) & 1, kb + (it + 1) * 32);
            asm volatile("cp.async.wait_group 1;\n" ::);
        } else {
            asm volatile("cp.async.wait_group 0;\n" ::);
        }
        __syncthreads();
        const int st = it & 1;
        const uint16_t* As0 = sh + st * TS;
        const uint16_t* As1 = sh + (2 + st) * TS;
        const uint16_t* Bs0 = sh + (PA * 2 + st) * TS;
        const uint16_t* Bs1 = sh + (PA * 2 + 2 + st) * TS;

#pragma unroll
        for (int ks = 0; ks < 32; ks += 16) {
            auto do_prod = [&](const uint16_t* Asb, const uint16_t* Bsb) {
                uint32_t af[4][4], bfr[4][2];
                const int kc = ks + 2 * tg;
#pragma unroll
                for (int mf = 0; mf < 4; mf++) {
                    int m = wm * 64 + mf * 16 + g;
                    af[mf][0] = *(const uint32_t*)&Asb[m * 40 + kc];
                    af[mf][1] = *(const uint32_t*)&Asb[(m + 8) * 40 + kc];
                    af[mf][2] = *(const uint32_t*)&Asb[m * 40 + kc + 8];
                    af[mf][3] = *(const uint32_t*)&Asb[(m + 8) * 40 + kc + 8];
                }
#pragma unroll
                for (int nf = 0; nf < 4; nf++) {
                    int n = wn * 32 + nf * 8 + g;
                    bfr[nf][0] = *(const uint32_t*)&Bsb[n * 40 + kc];
                    bfr[nf][1] = *(const uint32_t*)&Bsb[n * 40 + kc + 8];
                }
#pragma unroll
                for (int mf = 0; mf < 4; mf++)
#pragma unroll
                    for (int nf = 0; nf < 4; nf++)
                        asm volatile(
                            "mma.sync.aligned.m16n8k16.row.col.f32.bf16.bf16.f32 "
                            "{%0,%1,%2,%3},{%4,%5,%6,%7},{%8,%9},{%0,%1,%2,%3};"
                            : "+f"(acc[mf][nf][0]), "+f"(acc[mf][nf][1]),
                              "+f"(acc[mf][nf][2]), "+f"(acc[mf][nf][3])
                            : "r"(af[mf][0]), "r"(af[mf][1]), "r"(af[mf][2]),
                              "r"(af[mf][3]), "r"(bfr[nf][0]), "r"(bfr[nf][1]));
            };
            do_prod(As0, Bs0);
            if (NPROD >= 2) do_prod(As0, Bs1);
            if (NPROD == 3) do_prod(As1, Bs0);
        }
        __syncthreads();
    }

#pragma unroll
    for (int mf = 0; mf < 4; mf++)
#pragma unroll
        for (int nf = 0; nf < 4; nf++)
#pragma unroll
            for (int e = 0; e < 4; e++) {
                int m = m0 + wm * 64 + mf * 16 + g + (e >> 1) * 8;
                int c = j0 + wn * 32 + nf * 8 + 2 * tg + (e & 1);
                float v = acc[mf][nf][e];
                if (MODE == 0) {
                    ((float*)Cp)[(size_t)blockIdx.z * partStride + (size_t)m * ldc + c] = v;
                } else if (MODE == 1) {
                    v *= rsqrtf(scl[m] + 2.f);
                    bf16 h = __float2bfloat16(v);
                    ((bf16*)Cp)[(size_t)c * ldc + m] = h;
                    ((bf16*)C2p)[(size_t)c * ldc + m] =
                        __float2bfloat16(v - __bfloat162float(h));
                } else if (MODE == 2) {
                    ((float*)Cp)[(size_t)m * ldc + c] = v * scl[m];
                } else {
                    atomicAdd(&((float*)Cp)[(size_t)m * ldc + c], v);
                }
            }
}

// ---------------- host orchestration ----------------
#define SYM(p, s)                     \
    do {                              \
        void* _t = nullptr;           \
        cudaGetSymbolAddress(&_t, s); \
        p = (decltype(p))_t;          \
    } while (0)

extern "C" void kernel_launch(void* const* d_in, const int* in_sizes, int n_in,
                              void* d_out, int out_size) {
    const float* x_in = (const float*)d_in[0];
    const int* ei     = (const int*)d_in[1];
    const float* w_d0 = (const float*)d_in[3];
    const float* b_d0 = (const float*)d_in[4];
    const float* w_d  = (const float*)d_in[5];
    const float* b_d  = (const float*)d_in[6];
    const float* p_at = (const float*)d_in[7];
    const float* w_u  = (const float*)d_in[8];
    const float* b_u  = (const float*)d_in[9];
    float* out = (float*)d_out;
    const int E = in_sizes[1] / 2;

    bf16 *A1, *A2, *A3, *AT1, *AT2, *AT3;
    bf16 *Xhi, *Xlo, *Whi, *Wlo, *zhi, *zlo;
    float *X0, *X1, *X2, *Xc, *Cpart, *zf, *A1f;
    float *deg, *dinv0, *fil0, *sc, *pn;
    int *perm, *colmap, *rpi, *rpo, *cii, *cio, *curi, *curo, *cnt;
    SYM(A1, g_A1);   SYM(A2, g_A2);   SYM(A3, g_A3);
    SYM(AT1, g_AT1); SYM(AT2, g_AT2); SYM(AT3, g_AT3);
    SYM(Xhi, g_Xhi); SYM(Xlo, g_Xlo); SYM(Whi, g_Whi); SYM(Wlo, g_Wlo);
    SYM(zhi, g_zhi); SYM(zlo, g_zlo);
    SYM(X0, g_X0);   SYM(X1, g_X1);   SYM(X2, g_X2);
    SYM(Xc, g_Xc);   SYM(Cpart, g_Cpart);
    SYM(zf, g_z);    SYM(A1f, g_A1f);
    SYM(deg, g_deg); SYM(dinv0, g_dinv0); SYM(fil0, g_fil0);
    SYM(sc, g_s);    SYM(pn, g_pn);
    SYM(perm, g_perm); SYM(colmap, g_colmap);
    SYM(rpi, g_rpi); SYM(rpo, g_rpo); SYM(cii, g_cii); SYM(cio, g_cio);
    SYM(curi, g_curi); SYM(curo, g_curo); SYM(cnt, g_cnt);

    cudaFuncSetAttribute(mma_gemm<3, 1, 0>, cudaFuncAttributeMaxDynamicSharedMemorySize, 81920);
    cudaFuncSetAttribute(mma_gemm<3, 2, 0>, cudaFuncAttributeMaxDynamicSharedMemorySize, 81920);
    cudaFuncSetAttribute(mma_gemm<2, 0, 0>, cudaFuncAttributeMaxDynamicSharedMemorySize, 61440);
    cudaFuncSetAttribute(mma_gemm<1, 4, 1>, cudaFuncAttributeMaxDynamicSharedMemorySize, 40960);

    bf16* Alv[4] = {nullptr, A1, A2, A3};
    bf16* ATlv[4] = {nullptr, AT1, AT2, AT3};
    float* Xs[3] = {X0, X1, X2};
    const int ns[4] = {4096, 2048, 1024, 512};

    // ---- one-time zeroing ----
    cudaMemsetAsync(cnt, 0, 3 * N0 * sizeof(int));
    cudaMemsetAsync(colmap, 0xFF, 3 * N0 * sizeof(int));
    cudaMemsetAsync(deg, 0, 4 * N0 * sizeof(float));

    // ---- CSR build ----
    count_deg<<<cdiv(E, 256), 256>>>(ei, E, cnt);
    scan_build<<<1, 1024>>>(cnt, rpi, rpo, curi, curo);
    fill_csr<<<cdiv(E, 256), 256>>>(ei, E, curi, curo, cii, cio);
    lvl0_norm<<<N0 / 256, 256>>>(cnt, dinv0, fil0);

    // lvl-0 sparse GCN
    auto gcn0 = [&](const float* Xsrc, int Kin, const float* W, const float* bias,
                    float* Y, int relu) {
        if (Xsrc) split_pair<<<cdiv(N0 * Kin, 256), 256>>>(Xsrc, Xhi, Xlo, N0 * Kin);
        splitT<<<cdiv(Kin * 256, 256), 256>>>(W, Whi, Wlo, Kin);
        mma_gemm<3, 2, 0><<<dim3(2, N0 / 128), 256, 81920>>>(
            Xhi, Xlo, Kin, Whi, Wlo, Kin, zf, nullptr, 256, Kin, 0, dinv0, nullptr);
        spmv_gcn<<<N0 / 8, 256>>>(rpi, cii, zf, dinv0, fil0, bias, Y, relu);
    };
    // dense GCN levels 1..3 (input in Xhi/Xlo)
    auto gcn = [&](int lvl, const float* W, const float* bias, float* Y, int relu) {
        int n = ns[lvl];
        splitT<<<cdiv(CH * 256, 256), 256>>>(W, Whi, Wlo, CH);
        mma_gemm<3, 1, 0><<<dim3(2, n / 128), 256, 81920>>>(
            Xhi, Xlo, CH, Whi, Wlo, CH, zhi, zlo, n, CH, 0, deg + lvl * N0, nullptr);
        mma_gemm<2, 0, 0><<<dim3(2, n / 128, 4), 256, 61440>>>(
            ATlv[lvl], nullptr, n, zhi, zlo, n, Cpart, nullptr, 256, n / 4, n * 256,
            nullptr, nullptr);
        reduce_gcn<<<cdiv(n * 256, 256), 256>>>(Cpart, 4, n * 256, n, zhi, zlo,
                                                deg + lvl * N0, bias, Y, relu);
    };

    gcn0(x_in, 128, w_d0, b_d0, X0, 1);

    // ---- down path ----
    for (int i = 0; i < 3; i++) {
        int n = ns[i], k = ns[i + 1];
        int* pm = perm + i * 2048;
        int* cm = colmap + i * N0;
        const float* pvec = p_at + i * CH;

        score_kernel<<<n / 8 + 1, 256>>>(Xs[i], pvec, n, sc, pn);
        if (i == 0) sort_topk_kernel<4096><<<1, 1024>>>(sc, pm, cm);
        else if (i == 1) sort_topk_kernel<2048><<<1, 1024>>>(sc, pm, cm);
        else sort_topk_kernel<1024><<<1, 1024>>>(sc, pm, cm);
        gather_x_kernel<<<cdiv(k * CH, 256), 256>>>(Xs[i], Xhi, Xlo, pm, sc, pn, k);

        cudaMemsetAsync(A1f, 0, (size_t)k * k * sizeof(float));
        if (i == 0) {
            sparse_augment<<<k, 256>>>(pm, cm, rpo, cio, A1f, k);
            finalize_A1<<<dim3(k / 64, k / 64), 256>>>(A1f, A1, AT1, deg + N0, k);
        } else {
            mma_gemm<1, 4, 1><<<dim3(k / 128, k / 128, 4), 256, 40960>>>(
                Alv[i], nullptr, n, ATlv[i], nullptr, n, A1f, nullptr, k, n / 4, 0,
                nullptr, pm);
            finalize_aug<<<dim3(k / 64, k / 64), 256>>>(A1f, Alv[i], pm, k, n,
                                                        Alv[i + 1], ATlv[i + 1],
                                                        deg + (i + 1) * N0);
        }

        if (i < 2)
            gcn(i + 1, w_d + i * CH * CH, b_d + i * CH, Xs[i + 1], 1);
        else
            gcn(3, w_d + 2 * CH * CH, b_d + 2 * CH, Xc, 1);
    }

    // ---- up path ----
    for (int i = 0; i < 3; i++) {
        int j = 2 - i;
        int nj = ns[j];
        unpool_split<<<cdiv(nj * CH, 256), 256>>>(Xs[j], Xc, colmap + j * N0, nj, Xhi, Xlo);
        if (j == 0)
            gcn0(nullptr, CH, w_u + i * CH * CH, b_u + i * CH, Xc, 0);
        else
            gcn(j, w_u + i * CH * CH, b_u + i * CH, Xc, 1);
    }

    mean_part<<<32, 256>>>(Xc, Cpart);
    mean_final<<<1, 256>>>(Cpart, out);
}